// round 12
// baseline (speedup 1.0000x reference)
#include <cuda_runtime.h>
#include <cstdint>

#define CIN     32
#define COUT    32
#define KTAP    27
#define THREADS 416
#define NWARP   13
#define MAX_N   131072
#define BN_EPS  1e-3f

#define W_TILE  4096            // one tap's B tile: 32 rows x 128B
#define W_BYTES (KTAP * W_TILE) // 110592
#define ABUF    4096            // per-warp A buffer: 32 rows x 128B
#define NBUF    2
#define DYN_SMEM (1024 + W_BYTES + NWARP * NBUF * ABUF)   // 218112

// ---------------- device scratch ----------------
__device__ __align__(128) float g_xT[(size_t)MAX_N * CIN];   // x: [N][32] cin-permuted, tf32-rounded
__device__ __align__(128) float g_wpre[KTAP * 1024];         // pre-swizzled tf32 B tiles
__device__ __align__(128) int   g_neighT[(size_t)KTAP * MAX_N]; // neigh transposed [k][node]
__device__ __align__(128) float g_y[(size_t)COUT * MAX_N];   // pre-BN result [Cout][N]
__device__ float g_sum[COUT];
__device__ float g_sq[COUT];
__device__ unsigned g_done;

// cin permutation: storage float f (0..31) within a node row <-> original cin.
static __device__ __forceinline__ int cin_of_f(int f) {
    int s2 = f >> 4, tig = (f >> 2) & 3, e = f & 3;
    return 16 * s2 + 8 * (e >> 1) + 4 * (e & 1) + tig;
}

// ---------------- PTX helpers ----------------
static __device__ __forceinline__ uint32_t smem_u32(const void* p) {
    uint32_t a;
    asm("{ .reg .u64 t; cvta.to.shared.u64 t, %1; cvt.u32.u64 %0, t; }" : "=r"(a) : "l"(p));
    return a;
}
static __device__ __forceinline__ void cp16(uint32_t dst, const void* src) {
    asm volatile("cp.async.cg.shared.global [%0], [%1], 16;" :: "r"(dst), "l"(src) : "memory");
}
#define CP_COMMIT() asm volatile("cp.async.commit_group;" ::: "memory")

static __device__ __forceinline__ void lds4u(uint32_t& x, uint32_t& y, uint32_t& z, uint32_t& w,
                                             uint32_t a) {
    asm volatile("ld.shared.v4.b32 {%0,%1,%2,%3}, [%4];"
                 : "=r"(x), "=r"(y), "=r"(z), "=r"(w) : "r"(a));
}
static __device__ __forceinline__ uint32_t tf32_rna(float v) {
    uint32_t r;
    asm("cvt.rna.tf32.f32 %0, %1;" : "=r"(r) : "f"(v));
    return r;
}
static __device__ __forceinline__ void mma8(float* c, uint32_t a0, uint32_t a1, uint32_t a2,
                                            uint32_t a3, uint32_t b0, uint32_t b1) {
    asm volatile(
        "mma.sync.aligned.m16n8k8.row.col.f32.tf32.tf32.f32 "
        "{%0,%1,%2,%3}, {%4,%5,%6,%7}, {%8,%9}, {%0,%1,%2,%3};"
        : "+f"(c[0]), "+f"(c[1]), "+f"(c[2]), "+f"(c[3])
        : "r"(a0), "r"(a1), "r"(a2), "r"(a3), "r"(b0), "r"(b1));
}

// cooperative gather: one warp fills 32 rows (128B each); each cp.async covers
// 4 rows x 8 lanes -> 4 L2 lines per instruction; writes stay in one 512B window.
static __device__ __forceinline__ void gather32(uint32_t dst_buf, int idx_reg, int lane) {
    const int rsub  = lane >> 3;       // 0..3
    const int chunk = lane & 7;        // 16B chunk within row
#pragma unroll
    for (int j = 0; j < 8; ++j) {
        int row = j * 4 + rsub;
        int src_idx = __shfl_sync(0xffffffffu, idx_reg, row);
        const char* src = reinterpret_cast<const char*>(g_xT + (size_t)src_idx * CIN)
                          + (chunk << 4);
        uint32_t dst = dst_buf + (uint32_t)(row << 7)
                       + (uint32_t)((chunk ^ (row & 7)) << 4);
        cp16(dst, src);
    }
}

// ---------------- kernel 1: fused prep (transpose | neighT | wprep+init) ----------------
__global__ void prep_kernel(const float* __restrict__ in, const int* __restrict__ neigh,
                            const float* __restrict__ w, int N,
                            int nT, int nN, int nW) {
    int blk = blockIdx.x;
    if (blk < nT) {
        // transpose + cin-permute + tf32 RNA round: [Cin,N] -> [N][32]
        __shared__ float tile[32][33];
        int tx = threadIdx.x & 31, ty = threadIdx.x >> 5;
        int cm = cin_of_f(tx);
#pragma unroll 1
        for (int s = 0; s < 4; ++s) {
            int nb = (blk * 4 + s) * 32;
            if (nb >= N) break;
#pragma unroll
            for (int j = 0; j < 4; ++j) {
                int c = ty + j * 8, n = nb + tx;
                if (n < N) tile[c][tx] = in[(size_t)c * N + n];
            }
            __syncthreads();
#pragma unroll
            for (int j = 0; j < 4; ++j) {
                int nl = ty + j * 8, n = nb + nl;
                if (n < N)
                    g_xT[(size_t)n * CIN + tx] = __uint_as_float(tf32_rna(tile[cm][nl]));
            }
            __syncthreads();
        }
        return;
    }
    blk -= nT;
    if (blk < nN) {
        // neigh transpose [N][27] -> [27][N], 8 warps x 32 nodes per block
        __shared__ int sb[8][864];
        int warp = threadIdx.x >> 5, lane = threadIdx.x & 31;
        int base = (blk * 8 + warp) * 32;
        const long fb = (long)base * KTAP;
        const long total = (long)N * KTAP;
#pragma unroll
        for (int j = 0; j < KTAP; ++j) {
            long p = fb + j * 32 + lane;
            sb[warp][j * 32 + lane] = (p < total) ? neigh[p] : 0;
        }
        __syncwarp();
        int node = base + lane;
        if (node < N) {
#pragma unroll
            for (int k = 0; k < KTAP; ++k)
                g_neighT[(size_t)k * N + node] = sb[warp][lane * KTAP + k];
        }
        return;
    }
    blk -= nN;
    if (blk < nW) {
        if (blk == 0) {
            if (threadIdx.x < COUT) { g_sum[threadIdx.x] = 0.f; g_sq[threadIdx.x] = 0.f; }
            if (threadIdx.x == COUT) g_done = 0u;
        }
        int i = blk * blockDim.x + threadIdx.x;   // over 27*1024 elems
        if (i >= KTAP * 1024) return;
        int k = i >> 10, r = i & 1023;
        int n = r >> 5, f = r & 31;               // n = cout row, f = storage float
        int chunk = f >> 2, e = f & 3;
        int cin = cin_of_f(f);
        float v = w[((size_t)k * CIN + cin) * COUT + n];
        int cs = chunk ^ (n & 7);
        g_wpre[k * 1024 + n * 32 + cs * 4 + e] = __uint_as_float(tf32_rna(v));
    }
}

// ---------------- kernel 2: conv + fused BN stats + grid-sync + normalize ----------------
__global__ void __launch_bounds__(THREADS)
conv_mma_kernel(float* __restrict__ out, const float* __restrict__ gamma,
                const float* __restrict__ beta, int N, int nchunks) {
    extern __shared__ char dsm[];
    __shared__ float s_sum[COUT], s_sq[COUT];
    __shared__ float s_scale[COUT], s_shift[COUT];
    const int tid  = threadIdx.x;
    const int warp = tid >> 5, lane = tid & 31;
    const int gid  = lane >> 2, tig = lane & 3;

    const uint32_t sbase = (smem_u32(dsm) + 1023u) & ~1023u;
    const uint32_t wbase = sbase;
    const uint32_t abase = sbase + W_BYTES + (uint32_t)warp * (NBUF * ABUF);

    if (tid < COUT) { s_sum[tid] = 0.f; s_sq[tid] = 0.f; }

    // ---- load all 27 pre-swizzled B tiles (one time) ----
    for (int i = tid; i < W_BYTES / 16; i += THREADS)
        cp16(wbase + i * 16, reinterpret_cast<const char*>(g_wpre) + i * 16);
    CP_COMMIT();
    asm volatile("cp.async.wait_group 0;" ::: "memory");
    __syncthreads();

    float rs[4][2], rq[4][2];
#pragma unroll
    for (int nt = 0; nt < 4; ++nt) {
        rs[nt][0] = rs[nt][1] = 0.f;
        rq[nt][0] = rq[nt][1] = 0.f;
    }

    // per-warp work assignment, SM-striped
    const int wglob  = warp * gridDim.x + blockIdx.x;
    const int nwtot  = gridDim.x * NWARP;

    for (int ch = wglob; ch < nchunks; ch += nwtot) {
        const int base32 = ch << 5;
        const int mynode = base32 + lane;
        const bool nvalid = (mynode < N);

        float acc[2][4][4];
#pragma unroll
        for (int mt = 0; mt < 2; ++mt)
#pragma unroll
            for (int nt = 0; nt < 4; ++nt)
#pragma unroll
                for (int q = 0; q < 4; ++q) acc[mt][nt][q] = 0.f;

        // prologue: gather taps 0..1
#pragma unroll
        for (int k = 0; k < NBUF; ++k) {
            int idx = nvalid ? g_neighT[(size_t)k * N + mynode] : 0;
            gather32(abase + (uint32_t)k * ABUF, idx, lane);
            CP_COMMIT();
        }

        int b = 0;
#pragma unroll 1
        for (int k = 0; k < KTAP; ++k) {
            if (k < KTAP - 1) asm volatile("cp.async.wait_group 1;" ::: "memory");
            else              asm volatile("cp.async.wait_group 0;" ::: "memory");
            __syncwarp();

            const uint32_t abuf = abase + (uint32_t)b * ABUF;
            const uint32_t wtap = wbase + (uint32_t)k * W_TILE;
#pragma unroll
            for (int s2 = 0; s2 < 2; ++s2) {
                const uint32_t ch4 = (uint32_t)((((s2 << 2) | tig) ^ gid) << 4);
                uint32_t B0[4], B1[4], B2[4], B3[4];
#pragma unroll
                for (int nt = 0; nt < 4; ++nt)
                    lds4u(B0[nt], B1[nt], B2[nt], B3[nt],
                          wtap + (uint32_t)((nt * 8 + gid) * 128) + ch4);
#pragma unroll
                for (int mt = 0; mt < 2; ++mt) {
                    uint32_t hx, hy, hz, hw, gx, gy, gz, gw;
                    lds4u(hx, hy, hz, hw, abuf + (uint32_t)((mt * 16 + gid) * 128) + ch4);
                    lds4u(gx, gy, gz, gw, abuf + (uint32_t)((mt * 16 + gid + 8) * 128) + ch4);
#pragma unroll
                    for (int nt = 0; nt < 4; ++nt) {
                        mma8(acc[mt][nt], hx, gx, hy, gy, B0[nt], B1[nt]);
                        mma8(acc[mt][nt], hz, gz, hw, gw, B2[nt], B3[nt]);
                    }
                }
            }

            if (k + NBUF < KTAP) {
                __syncwarp();
                int idx = nvalid ? g_neighT[(size_t)(k + NBUF) * N + mynode] : 0;
                gather32(abuf, idx, lane);
                CP_COMMIT();
            }
            b ^= 1;
        }

        // epilogue: store y + accumulate BN stats in registers
#pragma unroll
        for (int mt = 0; mt < 2; ++mt) {
            int node = base32 + (mt << 4) + gid;
            bool v0 = (node < N), v1 = (node + 8 < N);
#pragma unroll
            for (int nt = 0; nt < 4; ++nt) {
                int cb = (nt << 3) + (tig << 1);
                if (v0) {
                    float a = acc[mt][nt][0], c = acc[mt][nt][1];
                    g_y[(size_t)cb * N + node]       = a;
                    g_y[(size_t)(cb + 1) * N + node] = c;
                    rs[nt][0] += a; rq[nt][0] += a * a;
                    rs[nt][1] += c; rq[nt][1] += c * c;
                }
                if (v1) {
                    float a = acc[mt][nt][2], c = acc[mt][nt][3];
                    g_y[(size_t)cb * N + node + 8]       = a;
                    g_y[(size_t)(cb + 1) * N + node + 8] = c;
                    rs[nt][0] += a; rq[nt][0] += a * a;
                    rs[nt][1] += c; rq[nt][1] += c * c;
                }
            }
        }
    }

    // ---- reduce BN stats: shuffle over gid, shared atomics, one global atomic per CTA ----
#pragma unroll
    for (int nt = 0; nt < 4; ++nt)
#pragma unroll
        for (int q = 0; q < 2; ++q) {
#pragma unroll
            for (int o = 4; o <= 16; o <<= 1) {
                rs[nt][q] += __shfl_xor_sync(~0u, rs[nt][q], o);
                rq[nt][q] += __shfl_xor_sync(~0u, rq[nt][q], o);
            }
        }
    if (gid == 0) {
#pragma unroll
        for (int nt = 0; nt < 4; ++nt)
#pragma unroll
            for (int q = 0; q < 2; ++q) {
                int cb = (nt << 3) + (tig << 1) + q;
                atomicAdd(&s_sum[cb], rs[nt][q]);
                atomicAdd(&s_sq[cb],  rq[nt][q]);
            }
    }
    __syncthreads();
    if (tid < COUT) {
        atomicAdd(&g_sum[tid], s_sum[tid]);
        atomicAdd(&g_sq[tid],  s_sq[tid]);
    }

    // ---- grid sync (all CTAs co-resident: grid <= #SM, 1 CTA/SM by smem) ----
    __threadfence();
    __syncthreads();
    if (tid == 0) {
        atomicAdd(&g_done, 1u);
        while (atomicAdd(&g_done, 0u) < (unsigned)gridDim.x) __nanosleep(64);
    }
    __syncthreads();
    __threadfence();

    // ---- finalize params (every CTA computes the same values) ----
    if (tid < COUT) {
        float mean = g_sum[tid] / (float)N;
        float var  = g_sq[tid] / (float)N - mean * mean;
        float inv  = rsqrtf(var + BN_EPS);
        float sc   = gamma[tid] * inv;
        s_scale[tid] = sc;
        s_shift[tid] = beta[tid] - mean * sc;
    }
    __syncthreads();

    // ---- normalize + write output (y is L2-hot) ----
    {
        int total4 = (COUT * N) >> 2;
        int per = (total4 + gridDim.x - 1) / gridDim.x;
        int lo = blockIdx.x * per;
        int hi = lo + per; if (hi > total4) hi = total4;
        for (int i = lo + tid; i < hi; i += THREADS) {
            int d = (i << 2) / N;
            float4 v = reinterpret_cast<const float4*>(g_y)[i];
            float sc = s_scale[d], sh = s_shift[d];
            v.x = v.x * sc + sh;
            v.y = v.y * sc + sh;
            v.z = v.z * sc + sh;
            v.w = v.w * sc + sh;
            reinterpret_cast<float4*>(out)[i] = v;
        }
    }
}

// ---------------- launch ----------------
extern "C" void kernel_launch(void* const* d_in, const int* in_sizes, int n_in,
                              void* d_out, int out_size) {
    const float* data_in = (const float*)d_in[0];   // [1, Cin, N, 1]
    const int*   neigh   = (const int*)d_in[1];     // [N, 27]
    const float* weight  = (const float*)d_in[2];   // [27, Cin, Cout]
    const float* gamma   = (const float*)d_in[3];
    const float* beta    = (const float*)d_in[4];
    float*       out     = (float*)d_out;

    const int N = in_sizes[0] / CIN;
    const int nchunks = (N + 31) / 32;

    int dev = 0, nsm = 148;
    cudaGetDevice(&dev);
    cudaDeviceGetAttribute(&nsm, cudaDevAttrMultiProcessorCount, dev);
    if (nsm <= 0) nsm = 148;
    int grid = nsm;
    int maxctas = (nchunks + NWARP - 1) / NWARP;
    if (grid > maxctas) grid = maxctas;

    cudaFuncSetAttribute(conv_mma_kernel,
                         cudaFuncAttributeMaxDynamicSharedMemorySize, DYN_SMEM);

    const int nT = (N + 127) / 128;                  // transpose blocks (4 subtiles each)
    const int nN = (N + 255) / 256;                  // neighT blocks
    const int nW = (KTAP * 1024 + 255) / 256;        // wprep blocks
    prep_kernel<<<nT + nN + nW, 256>>>(data_in, neigh, weight, N, nT, nN, nW);

    conv_mma_kernel<<<grid, THREADS, DYN_SMEM>>>(out, gamma, beta, N, nchunks);
}

// round 13
// speedup vs baseline: 1.0667x; 1.0667x over previous
#include <cuda_runtime.h>
#include <cstdint>

#define CIN     32
#define COUT    32
#define KTAP    27
#define THREADS 416
#define NWARP   13
#define MAX_N   131072
#define BN_EPS  1e-3f

#define W_TILE  4096            // one tap's B tile: 32 rows x 128B
#define W_BYTES (KTAP * W_TILE) // 110592
#define ABUF    4096            // per-warp A buffer: 32 rows x 128B
#define NBUF    2
#define DYN_SMEM (1024 + W_BYTES + NWARP * NBUF * ABUF)   // 218112

// ---------------- device scratch ----------------
__device__ __align__(128) float g_xT[(size_t)MAX_N * CIN];   // x: [N][32] cin-permuted, tf32-rounded
__device__ __align__(128) float g_wpre[KTAP * 1024];         // pre-swizzled tf32 B tiles
__device__ __align__(128) int   g_neighT[(size_t)KTAP * MAX_N]; // neigh transposed [k][node]
__device__ __align__(128) float g_y[(size_t)COUT * MAX_N];   // pre-BN result [Cout][N]
__device__ float g_sum[COUT];
__device__ float g_sq[COUT];

// cin permutation: storage float f (0..31) within a node row <-> original cin.
static __device__ __forceinline__ int cin_of_f(int f) {
    int s2 = f >> 4, tig = (f >> 2) & 3, e = f & 3;
    return 16 * s2 + 8 * (e >> 1) + 4 * (e & 1) + tig;
}

// ---------------- PTX helpers ----------------
static __device__ __forceinline__ uint32_t smem_u32(const void* p) {
    uint32_t a;
    asm("{ .reg .u64 t; cvta.to.shared.u64 t, %1; cvt.u32.u64 %0, t; }" : "=r"(a) : "l"(p));
    return a;
}
static __device__ __forceinline__ void cp16(uint32_t dst, const void* src) {
    asm volatile("cp.async.cg.shared.global [%0], [%1], 16;" :: "r"(dst), "l"(src) : "memory");
}
#define CP_COMMIT() asm volatile("cp.async.commit_group;" ::: "memory")

static __device__ __forceinline__ void lds4u(uint32_t& x, uint32_t& y, uint32_t& z, uint32_t& w,
                                             uint32_t a) {
    asm volatile("ld.shared.v4.b32 {%0,%1,%2,%3}, [%4];"
                 : "=r"(x), "=r"(y), "=r"(z), "=r"(w) : "r"(a));
}
static __device__ __forceinline__ uint32_t tf32_rna(float v) {
    uint32_t r;
    asm("cvt.rna.tf32.f32 %0, %1;" : "=r"(r) : "f"(v));
    return r;
}
static __device__ __forceinline__ void mma8(float* c, uint32_t a0, uint32_t a1, uint32_t a2,
                                            uint32_t a3, uint32_t b0, uint32_t b1) {
    asm volatile(
        "mma.sync.aligned.m16n8k8.row.col.f32.tf32.tf32.f32 "
        "{%0,%1,%2,%3}, {%4,%5,%6,%7}, {%8,%9}, {%0,%1,%2,%3};"
        : "+f"(c[0]), "+f"(c[1]), "+f"(c[2]), "+f"(c[3])
        : "r"(a0), "r"(a1), "r"(a2), "r"(a3), "r"(b0), "r"(b1));
}

// cooperative gather: one warp fills 32 rows (128B each); each cp.async covers
// 4 rows x 8 lanes -> 4 L2 lines per instruction; writes stay in one 512B window.
static __device__ __forceinline__ void gather32(uint32_t dst_buf, int idx_reg, int lane) {
    const int rsub  = lane >> 3;       // 0..3
    const int chunk = lane & 7;        // 16B chunk within row
#pragma unroll
    for (int j = 0; j < 8; ++j) {
        int row = j * 4 + rsub;
        int src_idx = __shfl_sync(0xffffffffu, idx_reg, row);
        const char* src = reinterpret_cast<const char*>(g_xT + (size_t)src_idx * CIN)
                          + (chunk << 4);
        uint32_t dst = dst_buf + (uint32_t)(row << 7)
                       + (uint32_t)((chunk ^ (row & 7)) << 4);
        cp16(dst, src);
    }
}

// ---------------- kernel 1: fused prep (transpose | neighT | wprep+init) ----------------
__global__ void prep_kernel(const float* __restrict__ in, const int* __restrict__ neigh,
                            const float* __restrict__ w, int N,
                            int nT, int nN, int nW) {
    int blk = blockIdx.x;
    if (blk < nT) {
        // transpose + cin-permute + tf32 RNA round: [Cin,N] -> [N][32]
        // 8 subtiles of 32 nodes per block
        __shared__ float tile[32][33];
        int tx = threadIdx.x & 31, ty = threadIdx.x >> 5;
        int cm = cin_of_f(tx);
#pragma unroll 1
        for (int s = 0; s < 8; ++s) {
            int nb = (blk * 8 + s) * 32;
            if (nb >= N) break;
#pragma unroll
            for (int j = 0; j < 4; ++j) {
                int c = ty + j * 8, n = nb + tx;
                if (n < N) tile[c][tx] = in[(size_t)c * N + n];
            }
            __syncthreads();
#pragma unroll
            for (int j = 0; j < 4; ++j) {
                int nl = ty + j * 8, n = nb + nl;
                if (n < N)
                    g_xT[(size_t)n * CIN + tx] = __uint_as_float(tf32_rna(tile[cm][nl]));
            }
            __syncthreads();
        }
        return;
    }
    blk -= nT;
    if (blk < nN) {
        // neigh transpose [N][27] -> [27][N], 8 warps x 32 nodes per block
        __shared__ int sb[8][864];
        int warp = threadIdx.x >> 5, lane = threadIdx.x & 31;
        int base = (blk * 8 + warp) * 32;
        const long fb = (long)base * KTAP;
        const long total = (long)N * KTAP;
#pragma unroll
        for (int j = 0; j < KTAP; ++j) {
            long p = fb + j * 32 + lane;
            sb[warp][j * 32 + lane] = (p < total) ? neigh[p] : 0;
        }
        __syncwarp();
        int node = base + lane;
        if (node < N) {
#pragma unroll
            for (int k = 0; k < KTAP; ++k)
                g_neighT[(size_t)k * N + node] = sb[warp][lane * KTAP + k];
        }
        return;
    }
    blk -= nN;
    if (blk < nW) {
        if (blk == 0 && threadIdx.x < COUT) {
            g_sum[threadIdx.x] = 0.f;
            g_sq[threadIdx.x]  = 0.f;
        }
        int i = blk * blockDim.x + threadIdx.x;   // over 27*1024 elems
        if (i >= KTAP * 1024) return;
        int k = i >> 10, r = i & 1023;
        int n = r >> 5, f = r & 31;               // n = cout row, f = storage float
        int chunk = f >> 2, e = f & 3;
        int cin = cin_of_f(f);
        float v = w[((size_t)k * CIN + cin) * COUT + n];
        int cs = chunk ^ (n & 7);
        g_wpre[k * 1024 + n * 32 + cs * 4 + e] = __uint_as_float(tf32_rna(v));
    }
}

// ---------------- kernel 2: gather + mma.sync tf32 conv + fused BN stats ----------------
__global__ void __launch_bounds__(THREADS)
conv_mma_kernel(int N, int nchunks) {
    extern __shared__ char dsm[];
    __shared__ float s_sum[COUT], s_sq[COUT];
    const int tid  = threadIdx.x;
    const int warp = tid >> 5, lane = tid & 31;
    const int gid  = lane >> 2, tig = lane & 3;

    const uint32_t sbase = (smem_u32(dsm) + 1023u) & ~1023u;
    const uint32_t wbase = sbase;
    const uint32_t abase = sbase + W_BYTES + (uint32_t)warp * (NBUF * ABUF);

    if (tid < COUT) { s_sum[tid] = 0.f; s_sq[tid] = 0.f; }

    // ---- load all 27 pre-swizzled B tiles (one time) ----
    for (int i = tid; i < W_BYTES / 16; i += THREADS)
        cp16(wbase + i * 16, reinterpret_cast<const char*>(g_wpre) + i * 16);
    CP_COMMIT();
    asm volatile("cp.async.wait_group 0;" ::: "memory");
    __syncthreads();

    float rs[4][2], rq[4][2];
#pragma unroll
    for (int nt = 0; nt < 4; ++nt) {
        rs[nt][0] = rs[nt][1] = 0.f;
        rq[nt][0] = rq[nt][1] = 0.f;
    }

    // per-warp work assignment, SM-striped
    const int wglob  = warp * gridDim.x + blockIdx.x;
    const int nwtot  = gridDim.x * NWARP;

    for (int ch = wglob; ch < nchunks; ch += nwtot) {
        const int base32 = ch << 5;
        const int mynode = base32 + lane;
        const bool nvalid = (mynode < N);

        float acc[2][4][4];
#pragma unroll
        for (int mt = 0; mt < 2; ++mt)
#pragma unroll
            for (int nt = 0; nt < 4; ++nt)
#pragma unroll
                for (int q = 0; q < 4; ++q) acc[mt][nt][q] = 0.f;

        // prologue: gather taps 0..1
#pragma unroll
        for (int k = 0; k < NBUF; ++k) {
            int idx = nvalid ? g_neighT[(size_t)k * N + mynode] : 0;
            gather32(abase + (uint32_t)k * ABUF, idx, lane);
            CP_COMMIT();
        }

        int b = 0;
#pragma unroll 1
        for (int k = 0; k < KTAP; ++k) {
            if (k < KTAP - 1) asm volatile("cp.async.wait_group 1;" ::: "memory");
            else              asm volatile("cp.async.wait_group 0;" ::: "memory");
            __syncwarp();

            const uint32_t abuf = abase + (uint32_t)b * ABUF;
            const uint32_t wtap = wbase + (uint32_t)k * W_TILE;
#pragma unroll
            for (int s2 = 0; s2 < 2; ++s2) {
                const uint32_t ch4 = (uint32_t)((((s2 << 2) | tig) ^ gid) << 4);
                uint32_t B0[4], B1[4], B2[4], B3[4];
#pragma unroll
                for (int nt = 0; nt < 4; ++nt)
                    lds4u(B0[nt], B1[nt], B2[nt], B3[nt],
                          wtap + (uint32_t)((nt * 8 + gid) * 128) + ch4);
#pragma unroll
                for (int mt = 0; mt < 2; ++mt) {
                    uint32_t hx, hy, hz, hw, gx, gy, gz, gw;
                    lds4u(hx, hy, hz, hw, abuf + (uint32_t)((mt * 16 + gid) * 128) + ch4);
                    lds4u(gx, gy, gz, gw, abuf + (uint32_t)((mt * 16 + gid + 8) * 128) + ch4);
#pragma unroll
                    for (int nt = 0; nt < 4; ++nt) {
                        mma8(acc[mt][nt], hx, gx, hy, gy, B0[nt], B1[nt]);
                        mma8(acc[mt][nt], hz, gz, hw, gw, B2[nt], B3[nt]);
                    }
                }
            }

            if (k + NBUF < KTAP) {
                __syncwarp();
                int idx = nvalid ? g_neighT[(size_t)(k + NBUF) * N + mynode] : 0;
                gather32(abuf, idx, lane);
                CP_COMMIT();
            }
            b ^= 1;
        }

        // epilogue: store y + accumulate BN stats in registers
#pragma unroll
        for (int mt = 0; mt < 2; ++mt) {
            int node = base32 + (mt << 4) + gid;
            bool v0 = (node < N), v1 = (node + 8 < N);
#pragma unroll
            for (int nt = 0; nt < 4; ++nt) {
                int cb = (nt << 3) + (tig << 1);
                if (v0) {
                    float a = acc[mt][nt][0], c = acc[mt][nt][1];
                    g_y[(size_t)cb * N + node]       = a;
                    g_y[(size_t)(cb + 1) * N + node] = c;
                    rs[nt][0] += a; rq[nt][0] += a * a;
                    rs[nt][1] += c; rq[nt][1] += c * c;
                }
                if (v1) {
                    float a = acc[mt][nt][2], c = acc[mt][nt][3];
                    g_y[(size_t)cb * N + node + 8]       = a;
                    g_y[(size_t)(cb + 1) * N + node + 8] = c;
                    rs[nt][0] += a; rq[nt][0] += a * a;
                    rs[nt][1] += c; rq[nt][1] += c * c;
                }
            }
        }
    }

    // ---- reduce BN stats: shuffle over gid, shared atomics, one global atomic per CTA ----
#pragma unroll
    for (int nt = 0; nt < 4; ++nt)
#pragma unroll
        for (int q = 0; q < 2; ++q) {
#pragma unroll
            for (int o = 4; o <= 16; o <<= 1) {
                rs[nt][q] += __shfl_xor_sync(~0u, rs[nt][q], o);
                rq[nt][q] += __shfl_xor_sync(~0u, rq[nt][q], o);
            }
        }
    if (gid == 0) {
#pragma unroll
        for (int nt = 0; nt < 4; ++nt)
#pragma unroll
            for (int q = 0; q < 2; ++q) {
                int cb = (nt << 3) + (tig << 1) + q;
                atomicAdd(&s_sum[cb], rs[nt][q]);
                atomicAdd(&s_sq[cb],  rq[nt][q]);
            }
    }
    __syncthreads();
    if (tid < COUT) {
        atomicAdd(&g_sum[tid], s_sum[tid]);
        atomicAdd(&g_sq[tid],  s_sq[tid]);
    }
}

// ---------------- kernel 3: finalize (per-block) + normalize, 4 float4 per thread --------
__global__ void norm_kernel(float* __restrict__ out, const float* __restrict__ gamma,
                            const float* __restrict__ beta, int N) {
    __shared__ float s_scale[COUT], s_shift[COUT];
    if (threadIdx.x < COUT) {
        int d = threadIdx.x;
        float mean = g_sum[d] / (float)N;
        float var  = g_sq[d] / (float)N - mean * mean;
        float inv  = rsqrtf(var + BN_EPS);
        float sc   = gamma[d] * inv;
        s_scale[d] = sc;
        s_shift[d] = beta[d] - mean * sc;
    }
    __syncthreads();
    const int total4 = (COUT * N) >> 2;
    const int nq = N >> 2;                       // float4s per channel (N % 4 == 0)
    int base = blockIdx.x * (blockDim.x * 4) + threadIdx.x;

    int   idx[4];
    float4 v[4];
    bool  ok[4];
#pragma unroll
    for (int u = 0; u < 4; ++u) {                // batch the 4 loads: MLP = 4
        idx[u] = base + u * blockDim.x;
        ok[u] = (idx[u] < total4);
        if (ok[u]) v[u] = reinterpret_cast<const float4*>(g_y)[idx[u]];
    }
#pragma unroll
    for (int u = 0; u < 4; ++u) {
        if (!ok[u]) continue;
        int d = idx[u] / nq;
        float sc = s_scale[d], sh = s_shift[d];
        v[u].x = v[u].x * sc + sh;
        v[u].y = v[u].y * sc + sh;
        v[u].z = v[u].z * sc + sh;
        v[u].w = v[u].w * sc + sh;
        reinterpret_cast<float4*>(out)[idx[u]] = v[u];
    }
}

// ---------------- launch ----------------
extern "C" void kernel_launch(void* const* d_in, const int* in_sizes, int n_in,
                              void* d_out, int out_size) {
    const float* data_in = (const float*)d_in[0];   // [1, Cin, N, 1]
    const int*   neigh   = (const int*)d_in[1];     // [N, 27]
    const float* weight  = (const float*)d_in[2];   // [27, Cin, Cout]
    const float* gamma   = (const float*)d_in[3];
    const float* beta    = (const float*)d_in[4];
    float*       out     = (float*)d_out;

    const int N = in_sizes[0] / CIN;
    const int nchunks = (N + 31) / 32;

    int dev = 0, nsm = 148;
    cudaGetDevice(&dev);
    cudaDeviceGetAttribute(&nsm, cudaDevAttrMultiProcessorCount, dev);
    if (nsm <= 0) nsm = 148;
    int grid = nsm;
    int maxctas = (nchunks + NWARP - 1) / NWARP;
    if (grid > maxctas) grid = maxctas;

    cudaFuncSetAttribute(conv_mma_kernel,
                         cudaFuncAttributeMaxDynamicSharedMemorySize, DYN_SMEM);

    const int nT = (N + 255) / 256;                  // transpose blocks (8 subtiles each)
    const int nN = (N + 255) / 256;                  // neighT blocks
    const int nW = (KTAP * 1024 + 255) / 256;        // wprep blocks
    prep_kernel<<<nT + nN + nW, 256>>>(data_in, neigh, weight, N, nT, nN, nW);

    conv_mma_kernel<<<grid, THREADS, DYN_SMEM>>>(N, nchunks);

    {
        int total4 = (COUT * N) / 4;
        int nblk = (total4 + 1023) / 1024;
        norm_kernel<<<nblk, 256>>>(out, gamma, beta, N);
    }
}

// round 14
// speedup vs baseline: 1.0963x; 1.0278x over previous
#include <cuda_runtime.h>
#include <cstdint>

#define CIN     32
#define COUT    32
#define KTAP    27
#define THREADS 416
#define NWARP   13
#define MAX_N   131072
#define BN_EPS  1e-3f

#define W_TILE  4096            // one tap's B tile: 32 rows x 128B
#define W_BYTES (KTAP * W_TILE) // 110592
#define ABUF    4096            // per-warp A buffer: 32 rows x 128B
#define NBUF    2
#define DYN_SMEM (1024 + W_BYTES + NWARP * NBUF * ABUF)   // 218112

// ---------------- device scratch ----------------
__device__ __align__(128) float g_xT[(size_t)MAX_N * CIN];   // x: [N][32] cin-permuted, tf32-rounded
__device__ __align__(128) float g_wpre[KTAP * 1024];         // pre-swizzled tf32 B tiles
__device__ __align__(128) int   g_neighT[(size_t)KTAP * MAX_N]; // neigh transposed [k][node]
__device__ __align__(128) float g_y[(size_t)COUT * MAX_N];   // pre-BN result [Cout][N]
__device__ float g_sum[COUT];
__device__ float g_sq[COUT];

// cin permutation: storage float f (0..31) within a node row <-> original cin.
static __device__ __forceinline__ int cin_of_f(int f) {
    int s2 = f >> 4, tig = (f >> 2) & 3, e = f & 3;
    return 16 * s2 + 8 * (e >> 1) + 4 * (e & 1) + tig;
}

// ---------------- PTX helpers ----------------
static __device__ __forceinline__ uint32_t smem_u32(const void* p) {
    uint32_t a;
    asm("{ .reg .u64 t; cvta.to.shared.u64 t, %1; cvt.u32.u64 %0, t; }" : "=r"(a) : "l"(p));
    return a;
}
static __device__ __forceinline__ void cp16(uint32_t dst, const void* src) {
    asm volatile("cp.async.cg.shared.global [%0], [%1], 16;" :: "r"(dst), "l"(src) : "memory");
}
#define CP_COMMIT() asm volatile("cp.async.commit_group;" ::: "memory")

static __device__ __forceinline__ void lds4u(uint32_t& x, uint32_t& y, uint32_t& z, uint32_t& w,
                                             uint32_t a) {
    asm volatile("ld.shared.v4.b32 {%0,%1,%2,%3}, [%4];"
                 : "=r"(x), "=r"(y), "=r"(z), "=r"(w) : "r"(a));
}
static __device__ __forceinline__ uint32_t tf32_rna(float v) {
    uint32_t r;
    asm("cvt.rna.tf32.f32 %0, %1;" : "=r"(r) : "f"(v));
    return r;
}
static __device__ __forceinline__ void mma8(float* c, uint32_t a0, uint32_t a1, uint32_t a2,
                                            uint32_t a3, uint32_t b0, uint32_t b1) {
    asm volatile(
        "mma.sync.aligned.m16n8k8.row.col.f32.tf32.tf32.f32 "
        "{%0,%1,%2,%3}, {%4,%5,%6,%7}, {%8,%9}, {%0,%1,%2,%3};"
        : "+f"(c[0]), "+f"(c[1]), "+f"(c[2]), "+f"(c[3])
        : "r"(a0), "r"(a1), "r"(a2), "r"(a3), "r"(b0), "r"(b1));
}

// cooperative gather: one warp fills 32 rows (128B each); each cp.async covers
// 4 rows x 8 lanes -> 4 L2 lines per instruction; writes stay in one 512B window.
static __device__ __forceinline__ void gather32(uint32_t dst_buf, int idx_reg, int lane) {
    const int rsub  = lane >> 3;       // 0..3
    const int chunk = lane & 7;        // 16B chunk within row
#pragma unroll
    for (int j = 0; j < 8; ++j) {
        int row = j * 4 + rsub;
        int src_idx = __shfl_sync(0xffffffffu, idx_reg, row);
        const char* src = reinterpret_cast<const char*>(g_xT + (size_t)src_idx * CIN)
                          + (chunk << 4);
        uint32_t dst = dst_buf + (uint32_t)(row << 7)
                       + (uint32_t)((chunk ^ (row & 7)) << 4);
        cp16(dst, src);
    }
}

// ---------------- kernel 1: fused prep (transpose | neighT | wprep+init) ----------------
__global__ void prep_kernel(const float* __restrict__ in, const int* __restrict__ neigh,
                            const float* __restrict__ w, int N,
                            int nT, int nN, int nW) {
    int blk = blockIdx.x;
    if (blk < nT) {
        // transpose + cin-permute + tf32 RNA round: [Cin,N] -> [N][32]
        // 4 subtiles of 32 nodes per block (R11 config — latency hidden by block count)
        __shared__ float tile[32][33];
        int tx = threadIdx.x & 31, ty = threadIdx.x >> 5;
        int cm = cin_of_f(tx);
#pragma unroll 1
        for (int s = 0; s < 4; ++s) {
            int nb = (blk * 4 + s) * 32;
            if (nb >= N) break;
#pragma unroll
            for (int j = 0; j < 4; ++j) {
                int c = ty + j * 8, n = nb + tx;
                if (n < N) tile[c][tx] = in[(size_t)c * N + n];
            }
            __syncthreads();
#pragma unroll
            for (int j = 0; j < 4; ++j) {
                int nl = ty + j * 8, n = nb + nl;
                if (n < N)
                    g_xT[(size_t)n * CIN + tx] = __uint_as_float(tf32_rna(tile[cm][nl]));
            }
            __syncthreads();
        }
        return;
    }
    blk -= nT;
    if (blk < nN) {
        // neigh transpose [N][27] -> [27][N], 8 warps x 32 nodes per block
        __shared__ int sb[8][864];
        int warp = threadIdx.x >> 5, lane = threadIdx.x & 31;
        int base = (blk * 8 + warp) * 32;
        const long fb = (long)base * KTAP;
        const long total = (long)N * KTAP;
#pragma unroll
        for (int j = 0; j < KTAP; ++j) {
            long p = fb + j * 32 + lane;
            sb[warp][j * 32 + lane] = (p < total) ? neigh[p] : 0;
        }
        __syncwarp();
        int node = base + lane;
        if (node < N) {
#pragma unroll
            for (int k = 0; k < KTAP; ++k)
                g_neighT[(size_t)k * N + node] = sb[warp][lane * KTAP + k];
        }
        return;
    }
    blk -= nN;
    if (blk < nW) {
        if (blk == 0 && threadIdx.x < COUT) {
            g_sum[threadIdx.x] = 0.f;
            g_sq[threadIdx.x]  = 0.f;
        }
        int i = blk * blockDim.x + threadIdx.x;   // over 27*1024 elems
        if (i >= KTAP * 1024) return;
        int k = i >> 10, r = i & 1023;
        int n = r >> 5, f = r & 31;               // n = cout row, f = storage float
        int chunk = f >> 2, e = f & 3;
        int cin = cin_of_f(f);
        float v = w[((size_t)k * CIN + cin) * COUT + n];
        int cs = chunk ^ (n & 7);
        g_wpre[k * 1024 + n * 32 + cs * 4 + e] = __uint_as_float(tf32_rna(v));
    }
}

// ---------------- kernel 2: gather + mma.sync tf32 conv + fused BN stats ----------------
__global__ void __launch_bounds__(THREADS)
conv_mma_kernel(int N, int nchunks) {
    extern __shared__ char dsm[];
    __shared__ float s_sum[COUT], s_sq[COUT];
    const int tid  = threadIdx.x;
    const int warp = tid >> 5, lane = tid & 31;
    const int gid  = lane >> 2, tig = lane & 3;

    const uint32_t sbase = (smem_u32(dsm) + 1023u) & ~1023u;
    const uint32_t wbase = sbase;
    const uint32_t abase = sbase + W_BYTES + (uint32_t)warp * (NBUF * ABUF);

    if (tid < COUT) { s_sum[tid] = 0.f; s_sq[tid] = 0.f; }

    // ---- load all 27 pre-swizzled B tiles (one time) ----
    for (int i = tid; i < W_BYTES / 16; i += THREADS)
        cp16(wbase + i * 16, reinterpret_cast<const char*>(g_wpre) + i * 16);
    CP_COMMIT();
    asm volatile("cp.async.wait_group 0;" ::: "memory");
    __syncthreads();

    float rs[4][2], rq[4][2];
#pragma unroll
    for (int nt = 0; nt < 4; ++nt) {
        rs[nt][0] = rs[nt][1] = 0.f;
        rq[nt][0] = rq[nt][1] = 0.f;
    }

    // per-warp work assignment, SM-striped
    const int wglob  = warp * gridDim.x + blockIdx.x;
    const int nwtot  = gridDim.x * NWARP;

    for (int ch = wglob; ch < nchunks; ch += nwtot) {
        const int base32 = ch << 5;
        const int mynode = base32 + lane;
        const bool nvalid = (mynode < N);

        float acc[2][4][4];
#pragma unroll
        for (int mt = 0; mt < 2; ++mt)
#pragma unroll
            for (int nt = 0; nt < 4; ++nt)
#pragma unroll
                for (int q = 0; q < 4; ++q) acc[mt][nt][q] = 0.f;

        // prologue: gather taps 0..1
#pragma unroll
        for (int k = 0; k < NBUF; ++k) {
            int idx = nvalid ? g_neighT[(size_t)k * N + mynode] : 0;
            gather32(abase + (uint32_t)k * ABUF, idx, lane);
            CP_COMMIT();
        }

        int b = 0;
#pragma unroll 1
        for (int k = 0; k < KTAP; ++k) {
            if (k < KTAP - 1) asm volatile("cp.async.wait_group 1;" ::: "memory");
            else              asm volatile("cp.async.wait_group 0;" ::: "memory");
            __syncwarp();

            const uint32_t abuf = abase + (uint32_t)b * ABUF;
            const uint32_t wtap = wbase + (uint32_t)k * W_TILE;
#pragma unroll
            for (int s2 = 0; s2 < 2; ++s2) {
                const uint32_t ch4 = (uint32_t)((((s2 << 2) | tig) ^ gid) << 4);
                uint32_t B0[4], B1[4], B2[4], B3[4];
#pragma unroll
                for (int nt = 0; nt < 4; ++nt)
                    lds4u(B0[nt], B1[nt], B2[nt], B3[nt],
                          wtap + (uint32_t)((nt * 8 + gid) * 128) + ch4);
#pragma unroll
                for (int mt = 0; mt < 2; ++mt) {
                    uint32_t hx, hy, hz, hw, gx, gy, gz, gw;
                    lds4u(hx, hy, hz, hw, abuf + (uint32_t)((mt * 16 + gid) * 128) + ch4);
                    lds4u(gx, gy, gz, gw, abuf + (uint32_t)((mt * 16 + gid + 8) * 128) + ch4);
#pragma unroll
                    for (int nt = 0; nt < 4; ++nt) {
                        mma8(acc[mt][nt], hx, gx, hy, gy, B0[nt], B1[nt]);
                        mma8(acc[mt][nt], hz, gz, hw, gw, B2[nt], B3[nt]);
                    }
                }
            }

            if (k + NBUF < KTAP) {
                __syncwarp();
                int idx = nvalid ? g_neighT[(size_t)(k + NBUF) * N + mynode] : 0;
                gather32(abuf, idx, lane);
                CP_COMMIT();
            }
            b ^= 1;
        }

        // epilogue: store y + accumulate BN stats in registers
#pragma unroll
        for (int mt = 0; mt < 2; ++mt) {
            int node = base32 + (mt << 4) + gid;
            bool v0 = (node < N), v1 = (node + 8 < N);
#pragma unroll
            for (int nt = 0; nt < 4; ++nt) {
                int cb = (nt << 3) + (tig << 1);
                if (v0) {
                    float a = acc[mt][nt][0], c = acc[mt][nt][1];
                    g_y[(size_t)cb * N + node]       = a;
                    g_y[(size_t)(cb + 1) * N + node] = c;
                    rs[nt][0] += a; rq[nt][0] += a * a;
                    rs[nt][1] += c; rq[nt][1] += c * c;
                }
                if (v1) {
                    float a = acc[mt][nt][2], c = acc[mt][nt][3];
                    g_y[(size_t)cb * N + node + 8]       = a;
                    g_y[(size_t)(cb + 1) * N + node + 8] = c;
                    rs[nt][0] += a; rq[nt][0] += a * a;
                    rs[nt][1] += c; rq[nt][1] += c * c;
                }
            }
        }
    }

    // ---- reduce BN stats: shuffle over gid, shared atomics, one global atomic per CTA ----
#pragma unroll
    for (int nt = 0; nt < 4; ++nt)
#pragma unroll
        for (int q = 0; q < 2; ++q) {
#pragma unroll
            for (int o = 4; o <= 16; o <<= 1) {
                rs[nt][q] += __shfl_xor_sync(~0u, rs[nt][q], o);
                rq[nt][q] += __shfl_xor_sync(~0u, rq[nt][q], o);
            }
        }
    if (gid == 0) {
#pragma unroll
        for (int nt = 0; nt < 4; ++nt)
#pragma unroll
            for (int q = 0; q < 2; ++q) {
                int cb = (nt << 3) + (tig << 1) + q;
                atomicAdd(&s_sum[cb], rs[nt][q]);
                atomicAdd(&s_sq[cb],  rq[nt][q]);
            }
    }
    __syncthreads();
    if (tid < COUT) {
        atomicAdd(&g_sum[tid], s_sum[tid]);
        atomicAdd(&g_sq[tid],  s_sq[tid]);
    }
}

// ---------------- kernel 3: finalize (per-block) + normalize, 4 float4 per thread --------
__global__ void norm_kernel(float* __restrict__ out, const float* __restrict__ gamma,
                            const float* __restrict__ beta, int N) {
    __shared__ float s_scale[COUT], s_shift[COUT];
    if (threadIdx.x < COUT) {
        int d = threadIdx.x;
        float mean = g_sum[d] / (float)N;
        float var  = g_sq[d] / (float)N - mean * mean;
        float inv  = rsqrtf(var + BN_EPS);
        float sc   = gamma[d] * inv;
        s_scale[d] = sc;
        s_shift[d] = beta[d] - mean * sc;
    }
    __syncthreads();
    const int total4 = (COUT * N) >> 2;
    const int nq = N >> 2;                       // float4s per channel (N % 4 == 0)
    int base = blockIdx.x * (blockDim.x * 4) + threadIdx.x;

    int    idx[4];
    float4 v[4];
    bool   ok[4];
#pragma unroll
    for (int u = 0; u < 4; ++u) {                // batch the 4 loads: MLP = 4
        idx[u] = base + u * blockDim.x;
        ok[u] = (idx[u] < total4);
        if (ok[u]) v[u] = reinterpret_cast<const float4*>(g_y)[idx[u]];
    }
#pragma unroll
    for (int u = 0; u < 4; ++u) {
        if (!ok[u]) continue;
        int d = idx[u] / nq;
        float sc = s_scale[d], sh = s_shift[d];
        v[u].x = v[u].x * sc + sh;
        v[u].y = v[u].y * sc + sh;
        v[u].z = v[u].z * sc + sh;
        v[u].w = v[u].w * sc + sh;
        reinterpret_cast<float4*>(out)[idx[u]] = v[u];
    }
}

// ---------------- launch ----------------
extern "C" void kernel_launch(void* const* d_in, const int* in_sizes, int n_in,
                              void* d_out, int out_size) {
    const float* data_in = (const float*)d_in[0];   // [1, Cin, N, 1]
    const int*   neigh   = (const int*)d_in[1];     // [N, 27]
    const float* weight  = (const float*)d_in[2];   // [27, Cin, Cout]
    const float* gamma   = (const float*)d_in[3];
    const float* beta    = (const float*)d_in[4];
    float*       out     = (float*)d_out;

    const int N = in_sizes[0] / CIN;
    const int nchunks = (N + 31) / 32;

    int dev = 0, nsm = 148;
    cudaGetDevice(&dev);
    cudaDeviceGetAttribute(&nsm, cudaDevAttrMultiProcessorCount, dev);
    if (nsm <= 0) nsm = 148;
    int grid = nsm;
    int maxctas = (nchunks + NWARP - 1) / NWARP;
    if (grid > maxctas) grid = maxctas;

    cudaFuncSetAttribute(conv_mma_kernel,
                         cudaFuncAttributeMaxDynamicSharedMemorySize, DYN_SMEM);

    const int nT = (N + 127) / 128;                  // transpose blocks (4 subtiles each)
    const int nN = (N + 255) / 256;                  // neighT blocks
    const int nW = (KTAP * 1024 + 255) / 256;        // wprep blocks
    prep_kernel<<<nT + nN + nW, 256>>>(data_in, neigh, weight, N, nT, nN, nW);

    conv_mma_kernel<<<grid, THREADS, DYN_SMEM>>>(N, nchunks);

    {
        int total4 = (COUT * N) / 4;
        int nblk = (total4 + 1023) / 1024;
        norm_kernel<<<nblk, 256>>>(out, gamma, beta, N);
    }
}

// round 15
// speedup vs baseline: 1.1176x; 1.0195x over previous
#include <cuda_runtime.h>
#include <cstdint>

#define CIN     32
#define COUT    32
#define KTAP    27
#define THREADS 416
#define NWARP   13
#define MAX_N   131072
#define BN_EPS  1e-3f

#define W_TILE  4096            // one tap's B tile: 32 rows x 128B
#define W_BYTES (KTAP * W_TILE) // 110592
#define ABUF    4096            // per-warp A buffer: 32 rows x 128B
#define NBUF    2
#define DYN_SMEM (1024 + W_BYTES + NWARP * NBUF * ABUF)   // 218112

// ---------------- device scratch ----------------
__device__ __align__(128) float g_xT[(size_t)MAX_N * CIN];   // x: [N][32] cin-permuted, tf32-rounded
__device__ __align__(128) float g_wpre[KTAP * 1024];         // pre-swizzled tf32 B tiles
__device__ __align__(128) int   g_neighT[(size_t)KTAP * MAX_N]; // neigh transposed [k][node]
__device__ __align__(128) float g_y[(size_t)COUT * MAX_N];   // pre-BN result [Cout][N]
__device__ float g_sum[COUT];
__device__ float g_sq[COUT];

// cin permutation: storage float f (0..31) within a node row <-> original cin.
static __device__ __forceinline__ int cin_of_f(int f) {
    int s2 = f >> 4, tig = (f >> 2) & 3, e = f & 3;
    return 16 * s2 + 8 * (e >> 1) + 4 * (e & 1) + tig;
}

// ---------------- PTX helpers ----------------
static __device__ __forceinline__ uint32_t smem_u32(const void* p) {
    uint32_t a;
    asm("{ .reg .u64 t; cvta.to.shared.u64 t, %1; cvt.u32.u64 %0, t; }" : "=r"(a) : "l"(p));
    return a;
}
static __device__ __forceinline__ void cp16(uint32_t dst, const void* src) {
    asm volatile("cp.async.cg.shared.global [%0], [%1], 16;" :: "r"(dst), "l"(src) : "memory");
}
#define CP_COMMIT() asm volatile("cp.async.commit_group;" ::: "memory")

static __device__ __forceinline__ void lds4u(uint32_t& x, uint32_t& y, uint32_t& z, uint32_t& w,
                                             uint32_t a) {
    asm volatile("ld.shared.v4.b32 {%0,%1,%2,%3}, [%4];"
                 : "=r"(x), "=r"(y), "=r"(z), "=r"(w) : "r"(a));
}
static __device__ __forceinline__ uint32_t tf32_rna(float v) {
    uint32_t r;
    asm("cvt.rna.tf32.f32 %0, %1;" : "=r"(r) : "f"(v));
    return r;
}
static __device__ __forceinline__ void mma8(float* c, uint32_t a0, uint32_t a1, uint32_t a2,
                                            uint32_t a3, uint32_t b0, uint32_t b1) {
    asm volatile(
        "mma.sync.aligned.m16n8k8.row.col.f32.tf32.tf32.f32 "
        "{%0,%1,%2,%3}, {%4,%5,%6,%7}, {%8,%9}, {%0,%1,%2,%3};"
        : "+f"(c[0]), "+f"(c[1]), "+f"(c[2]), "+f"(c[3])
        : "r"(a0), "r"(a1), "r"(a2), "r"(a3), "r"(b0), "r"(b1));
}

// cooperative gather: one warp fills 32 rows (128B each); each cp.async covers
// 4 rows x 8 lanes -> 4 L2 lines per instruction; writes stay in one 512B window.
static __device__ __forceinline__ void gather32(uint32_t dst_buf, int idx_reg, int lane) {
    const int rsub  = lane >> 3;       // 0..3
    const int chunk = lane & 7;        // 16B chunk within row
#pragma unroll
    for (int j = 0; j < 8; ++j) {
        int row = j * 4 + rsub;
        int src_idx = __shfl_sync(0xffffffffu, idx_reg, row);
        const char* src = reinterpret_cast<const char*>(g_xT + (size_t)src_idx * CIN)
                          + (chunk << 4);
        uint32_t dst = dst_buf + (uint32_t)(row << 7)
                       + (uint32_t)((chunk ^ (row & 7)) << 4);
        cp16(dst, src);
    }
}

// ---------------- kernel 1: fused prep (transpose | neighT | wprep+init) ----------------
__global__ void prep_kernel(const float* __restrict__ in, const int* __restrict__ neigh,
                            const float* __restrict__ w, int N,
                            int nT, int nN, int nW) {
    // union'd shared buffer: transpose tiles (16896B) or neighT staging (27648B)
    __shared__ __align__(16) char sbuf[8 * 864 * 4];
    int blk = blockIdx.x;
    int t = threadIdx.x;

    if (blk < nT) {
        // transpose + cin-permute + tf32 RNA round: [Cin,N] -> [N][32]
        // 4 subtiles of 32 nodes; vectorized LDG.128 load phase, single barrier.
        float* tb = reinterpret_cast<float*>(sbuf);   // [4][32][33]
        const int c8 = t >> 3, q = t & 7;
        const bool n4 = ((N & 3) == 0);

        float4 v[4];
        bool okv[4];
#pragma unroll
        for (int s = 0; s < 4; ++s) {
            int nb = (blk * 4 + s) * 32;
            okv[s] = n4 && (nb + 32 <= N);
            if (okv[s])
                v[s] = *reinterpret_cast<const float4*>(in + (size_t)c8 * N + nb + 4 * q);
        }
#pragma unroll
        for (int s = 0; s < 4; ++s) {
            int nb = (blk * 4 + s) * 32;
            float* tr = tb + s * 1056 + c8 * 33;
            if (okv[s]) {
                tr[4 * q + 0] = v[s].x;
                tr[4 * q + 1] = v[s].y;
                tr[4 * q + 2] = v[s].z;
                tr[4 * q + 3] = v[s].w;
            } else if (nb < N) {
#pragma unroll
                for (int e = 0; e < 4; ++e) {
                    int n = nb + 4 * q + e;
                    if (n < N) tr[4 * q + e] = in[(size_t)c8 * N + n];
                }
            }
        }
        __syncthreads();

        const int tx = t & 31, ty = t >> 5;
        const int cm = cin_of_f(tx);
#pragma unroll
        for (int s = 0; s < 4; ++s) {
            int nb = (blk * 4 + s) * 32;
            const float* tr = tb + s * 1056 + cm * 33;
#pragma unroll
            for (int j = 0; j < 4; ++j) {
                int nl = ty + 8 * j, n = nb + nl;
                if (n < N)
                    g_xT[(size_t)n * CIN + tx] = __uint_as_float(tf32_rna(tr[nl]));
            }
        }
        return;
    }
    blk -= nT;
    if (blk < nN) {
        // neigh transpose [N][27] -> [27][N], 8 warps x 32 nodes per block
        // vectorized int4 staging (864 ints = 216 int4 per warp)
        int warp = t >> 5, lane = t & 31;
        int* sw = reinterpret_cast<int*>(sbuf) + warp * 864;
        int base = (blk * 8 + warp) * 32;

        if (base + 32 <= N) {
            const int4* src = reinterpret_cast<const int4*>(neigh + (size_t)base * KTAP);
#pragma unroll
            for (int j = 0; j < 7; ++j) {
                int idx = j * 32 + lane;
                if (idx < 216) {
                    int4 vv = src[idx];
                    *reinterpret_cast<int4*>(sw + idx * 4) = vv;
                }
            }
        } else {
            const long fb = (long)base * KTAP;
            const long total = (long)N * KTAP;
#pragma unroll
            for (int j = 0; j < KTAP; ++j) {
                long p = fb + j * 32 + lane;
                sw[j * 32 + lane] = (p < total) ? neigh[p] : 0;
            }
        }
        __syncwarp();
        int node = base + lane;
        if (node < N) {
#pragma unroll
            for (int k = 0; k < KTAP; ++k)
                g_neighT[(size_t)k * N + node] = sw[lane * KTAP + k];  // stride-27: conflict-free
        }
        return;
    }
    blk -= nN;
    if (blk < nW) {
        if (blk == 0 && t < COUT) {
            g_sum[t] = 0.f;
            g_sq[t]  = 0.f;
        }
        int i = blk * blockDim.x + t;             // over 27*1024 elems
        if (i >= KTAP * 1024) return;
        int k = i >> 10, r = i & 1023;
        int n = r >> 5, f = r & 31;               // n = cout row, f = storage float
        int chunk = f >> 2, e = f & 3;
        int cin = cin_of_f(f);
        float v = w[((size_t)k * CIN + cin) * COUT + n];
        int cs = chunk ^ (n & 7);
        g_wpre[k * 1024 + n * 32 + cs * 4 + e] = __uint_as_float(tf32_rna(v));
    }
}

// ---------------- kernel 2: gather + mma.sync tf32 conv + fused BN stats ----------------
__global__ void __launch_bounds__(THREADS)
conv_mma_kernel(int N, int nchunks) {
    extern __shared__ char dsm[];
    __shared__ float s_sum[COUT], s_sq[COUT];
    const int tid  = threadIdx.x;
    const int warp = tid >> 5, lane = tid & 31;
    const int gid  = lane >> 2, tig = lane & 3;

    const uint32_t sbase = (smem_u32(dsm) + 1023u) & ~1023u;
    const uint32_t wbase = sbase;
    const uint32_t abase = sbase + W_BYTES + (uint32_t)warp * (NBUF * ABUF);

    if (tid < COUT) { s_sum[tid] = 0.f; s_sq[tid] = 0.f; }

    // ---- load all 27 pre-swizzled B tiles (one time) ----
    for (int i = tid; i < W_BYTES / 16; i += THREADS)
        cp16(wbase + i * 16, reinterpret_cast<const char*>(g_wpre) + i * 16);
    CP_COMMIT();
    asm volatile("cp.async.wait_group 0;" ::: "memory");
    __syncthreads();

    float rs[4][2], rq[4][2];
#pragma unroll
    for (int nt = 0; nt < 4; ++nt) {
        rs[nt][0] = rs[nt][1] = 0.f;
        rq[nt][0] = rq[nt][1] = 0.f;
    }

    // per-warp work assignment, SM-striped
    const int wglob  = warp * gridDim.x + blockIdx.x;
    const int nwtot  = gridDim.x * NWARP;

    for (int ch = wglob; ch < nchunks; ch += nwtot) {
        const int base32 = ch << 5;
        const int mynode = base32 + lane;
        const bool nvalid = (mynode < N);

        float acc[2][4][4];
#pragma unroll
        for (int mt = 0; mt < 2; ++mt)
#pragma unroll
            for (int nt = 0; nt < 4; ++nt)
#pragma unroll
                for (int q = 0; q < 4; ++q) acc[mt][nt][q] = 0.f;

        // prologue: gather taps 0..1
#pragma unroll
        for (int k = 0; k < NBUF; ++k) {
            int idx = nvalid ? g_neighT[(size_t)k * N + mynode] : 0;
            gather32(abase + (uint32_t)k * ABUF, idx, lane);
            CP_COMMIT();
        }

        int b = 0;
#pragma unroll 1
        for (int k = 0; k < KTAP; ++k) {
            if (k < KTAP - 1) asm volatile("cp.async.wait_group 1;" ::: "memory");
            else              asm volatile("cp.async.wait_group 0;" ::: "memory");
            __syncwarp();

            const uint32_t abuf = abase + (uint32_t)b * ABUF;
            const uint32_t wtap = wbase + (uint32_t)k * W_TILE;
#pragma unroll
            for (int s2 = 0; s2 < 2; ++s2) {
                const uint32_t ch4 = (uint32_t)((((s2 << 2) | tig) ^ gid) << 4);
                uint32_t B0[4], B1[4], B2[4], B3[4];
#pragma unroll
                for (int nt = 0; nt < 4; ++nt)
                    lds4u(B0[nt], B1[nt], B2[nt], B3[nt],
                          wtap + (uint32_t)((nt * 8 + gid) * 128) + ch4);
#pragma unroll
                for (int mt = 0; mt < 2; ++mt) {
                    uint32_t hx, hy, hz, hw, gx, gy, gz, gw;
                    lds4u(hx, hy, hz, hw, abuf + (uint32_t)((mt * 16 + gid) * 128) + ch4);
                    lds4u(gx, gy, gz, gw, abuf + (uint32_t)((mt * 16 + gid + 8) * 128) + ch4);
#pragma unroll
                    for (int nt = 0; nt < 4; ++nt) {
                        mma8(acc[mt][nt], hx, gx, hy, gy, B0[nt], B1[nt]);
                        mma8(acc[mt][nt], hz, gz, hw, gw, B2[nt], B3[nt]);
                    }
                }
            }

            if (k + NBUF < KTAP) {
                __syncwarp();
                int idx = nvalid ? g_neighT[(size_t)(k + NBUF) * N + mynode] : 0;
                gather32(abuf, idx, lane);
                CP_COMMIT();
            }
            b ^= 1;
        }

        // epilogue: store y + accumulate BN stats in registers
#pragma unroll
        for (int mt = 0; mt < 2; ++mt) {
            int node = base32 + (mt << 4) + gid;
            bool v0 = (node < N), v1 = (node + 8 < N);
#pragma unroll
            for (int nt = 0; nt < 4; ++nt) {
                int cb = (nt << 3) + (tig << 1);
                if (v0) {
                    float a = acc[mt][nt][0], c = acc[mt][nt][1];
                    g_y[(size_t)cb * N + node]       = a;
                    g_y[(size_t)(cb + 1) * N + node] = c;
                    rs[nt][0] += a; rq[nt][0] += a * a;
                    rs[nt][1] += c; rq[nt][1] += c * c;
                }
                if (v1) {
                    float a = acc[mt][nt][2], c = acc[mt][nt][3];
                    g_y[(size_t)cb * N + node + 8]       = a;
                    g_y[(size_t)(cb + 1) * N + node + 8] = c;
                    rs[nt][0] += a; rq[nt][0] += a * a;
                    rs[nt][1] += c; rq[nt][1] += c * c;
                }
            }
        }
    }

    // ---- reduce BN stats: shuffle over gid, shared atomics, one global atomic per CTA ----
#pragma unroll
    for (int nt = 0; nt < 4; ++nt)
#pragma unroll
        for (int q = 0; q < 2; ++q) {
#pragma unroll
            for (int o = 4; o <= 16; o <<= 1) {
                rs[nt][q] += __shfl_xor_sync(~0u, rs[nt][q], o);
                rq[nt][q] += __shfl_xor_sync(~0u, rq[nt][q], o);
            }
        }
    if (gid == 0) {
#pragma unroll
        for (int nt = 0; nt < 4; ++nt)
#pragma unroll
            for (int q = 0; q < 2; ++q) {
                int cb = (nt << 3) + (tig << 1) + q;
                atomicAdd(&s_sum[cb], rs[nt][q]);
                atomicAdd(&s_sq[cb],  rq[nt][q]);
            }
    }
    __syncthreads();
    if (tid < COUT) {
        atomicAdd(&g_sum[tid], s_sum[tid]);
        atomicAdd(&g_sq[tid],  s_sq[tid]);
    }
}

// ---------------- kernel 3: finalize (per-block) + normalize, 4 float4 per thread --------
__global__ void norm_kernel(float* __restrict__ out, const float* __restrict__ gamma,
                            const float* __restrict__ beta, int N) {
    __shared__ float s_scale[COUT], s_shift[COUT];
    if (threadIdx.x < COUT) {
        int d = threadIdx.x;
        float mean = g_sum[d] / (float)N;
        float var  = g_sq[d] / (float)N - mean * mean;
        float inv  = rsqrtf(var + BN_EPS);
        float sc   = gamma[d] * inv;
        s_scale[d] = sc;
        s_shift[d] = beta[d] - mean * sc;
    }
    __syncthreads();
    const int total4 = (COUT * N) >> 2;
    const int nq = N >> 2;                       // float4s per channel (N % 4 == 0)
    int base = blockIdx.x * (blockDim.x * 4) + threadIdx.x;

    int    idx[4];
    float4 v[4];
    bool   ok[4];
#pragma unroll
    for (int u = 0; u < 4; ++u) {                // batch the 4 loads: MLP = 4
        idx[u] = base + u * blockDim.x;
        ok[u] = (idx[u] < total4);
        if (ok[u]) v[u] = reinterpret_cast<const float4*>(g_y)[idx[u]];
    }
#pragma unroll
    for (int u = 0; u < 4; ++u) {
        if (!ok[u]) continue;
        int d = idx[u] / nq;
        float sc = s_scale[d], sh = s_shift[d];
        v[u].x = v[u].x * sc + sh;
        v[u].y = v[u].y * sc + sh;
        v[u].z = v[u].z * sc + sh;
        v[u].w = v[u].w * sc + sh;
        reinterpret_cast<float4*>(out)[idx[u]] = v[u];
    }
}

// ---------------- launch ----------------
extern "C" void kernel_launch(void* const* d_in, const int* in_sizes, int n_in,
                              void* d_out, int out_size) {
    const float* data_in = (const float*)d_in[0];   // [1, Cin, N, 1]
    const int*   neigh   = (const int*)d_in[1];     // [N, 27]
    const float* weight  = (const float*)d_in[2];   // [27, Cin, Cout]
    const float* gamma   = (const float*)d_in[3];
    const float* beta    = (const float*)d_in[4];
    float*       out     = (float*)d_out;

    const int N = in_sizes[0] / CIN;
    const int nchunks = (N + 31) / 32;

    int dev = 0, nsm = 148;
    cudaGetDevice(&dev);
    cudaDeviceGetAttribute(&nsm, cudaDevAttrMultiProcessorCount, dev);
    if (nsm <= 0) nsm = 148;
    int grid = nsm;
    int maxctas = (nchunks + NWARP - 1) / NWARP;
    if (grid > maxctas) grid = maxctas;

    cudaFuncSetAttribute(conv_mma_kernel,
                         cudaFuncAttributeMaxDynamicSharedMemorySize, DYN_SMEM);

    const int nT = (N + 127) / 128;                  // transpose blocks (4 subtiles each)
    const int nN = (N + 255) / 256;                  // neighT blocks
    const int nW = (KTAP * 1024 + 255) / 256;        // wprep blocks
    prep_kernel<<<nT + nN + nW, 256>>>(data_in, neigh, weight, N, nT, nN, nW);

    conv_mma_kernel<<<grid, THREADS, DYN_SMEM>>>(N, nchunks);

    {
        int total4 = (COUT * N) / 4;
        int nblk = (total4 + 1023) / 1024;
        norm_kernel<<<nblk, 256>>>(out, gamma, beta, N);
    }
}

// round 16
// speedup vs baseline: 1.4994x; 1.3416x over previous
#include <cuda_runtime.h>
#include <cuda_fp16.h>
#include <cstdint>

#define CIN     32
#define COUT    32
#define KTAP    27
#define THREADS 416
#define NWARP   13
#define MAX_N   131072
#define BN_EPS  1e-3f

#define W_TILE  2048            // one tap's B tile: 32 rows x 64B (fp16)
#define W_BYTES (KTAP * W_TILE) // 55296
#define ABUF    2048            // per-warp A buffer: 32 rows x 64B
#define NBUF    2
#define DYN_SMEM (1024 + W_BYTES + NWARP * NBUF * ABUF)   // 109568

// ---------------- device scratch ----------------
__device__ __align__(128) __half g_xTh[(size_t)MAX_N * CIN];  // x: [N][32] fp16, k-permuted
__device__ __align__(128) __half g_wpreh[KTAP * 1024];        // B tiles fp16, swizzled image
__device__ __align__(128) int    g_neighT[(size_t)KTAP * MAX_N];
__device__ __align__(128) float  g_y[(size_t)COUT * MAX_N];   // pre-BN result [Cout][N]
__device__ float g_sum[COUT];
__device__ float g_sq[COUT];

// k-permutation: storage half f (0..31) <-> original cin.
// chunk t = f>>3 holds k = {2t,2t+1, 2t+8,2t+9, 2t+16,2t+17, 2t+24,2t+25}
static __device__ __forceinline__ int cin_of_f(int f) {
    int t8 = f >> 3, j = f & 7;
    return 2 * t8 + 8 * (j >> 1) + (j & 1);
}

// ---------------- PTX helpers ----------------
static __device__ __forceinline__ uint32_t smem_u32(const void* p) {
    uint32_t a;
    asm("{ .reg .u64 t; cvta.to.shared.u64 t, %1; cvt.u32.u64 %0, t; }" : "=r"(a) : "l"(p));
    return a;
}
static __device__ __forceinline__ void cp16(uint32_t dst, const void* src) {
    asm volatile("cp.async.cg.shared.global [%0], [%1], 16;" :: "r"(dst), "l"(src) : "memory");
}
#define CP_COMMIT() asm volatile("cp.async.commit_group;" ::: "memory")

static __device__ __forceinline__ void lds4u(uint32_t& x, uint32_t& y, uint32_t& z, uint32_t& w,
                                             uint32_t a) {
    asm volatile("ld.shared.v4.b32 {%0,%1,%2,%3}, [%4];"
                 : "=r"(x), "=r"(y), "=r"(z), "=r"(w) : "r"(a));
}
static __device__ __forceinline__ void mma16(float* c, uint32_t a0, uint32_t a1, uint32_t a2,
                                             uint32_t a3, uint32_t b0, uint32_t b1) {
    asm volatile(
        "mma.sync.aligned.m16n8k16.row.col.f32.f16.f16.f32 "
        "{%0,%1,%2,%3}, {%4,%5,%6,%7}, {%8,%9}, {%0,%1,%2,%3};"
        : "+f"(c[0]), "+f"(c[1]), "+f"(c[2]), "+f"(c[3])
        : "r"(a0), "r"(a1), "r"(a2), "r"(a3), "r"(b0), "r"(b1));
}

// cooperative gather: one warp fills 32 rows (64B each); each cp.async covers
// 8 rows x 4 lanes; writes conflict-free (swizzle chunk ^ ((row>>1)&3)).
static __device__ __forceinline__ void gather32h(uint32_t dst_buf, int idx_reg, int lane) {
    const int rsub  = lane >> 2;       // 0..7
    const int chunk = lane & 3;        // 16B chunk within 64B row
#pragma unroll
    for (int j = 0; j < 4; ++j) {
        int row = j * 8 + rsub;
        int src_idx = __shfl_sync(0xffffffffu, idx_reg, row);
        const char* src = reinterpret_cast<const char*>(g_xTh + (size_t)src_idx * CIN)
                          + (chunk << 4);
        uint32_t dst = dst_buf + (uint32_t)(row << 6)
                       + (uint32_t)((chunk ^ ((row >> 1) & 3)) << 4);
        cp16(dst, src);
    }
}

// ---------------- kernel 1: fused prep (transpose | neighT | wprep+init) ----------------
__global__ void prep_kernel(const float* __restrict__ in, const int* __restrict__ neigh,
                            const float* __restrict__ w, int N,
                            int nT, int nN, int nW) {
    __shared__ __align__(16) char sbuf[8 * 864 * 4];
    int blk = blockIdx.x;
    int t = threadIdx.x;

    if (blk < nT) {
        // transpose + k-permute + fp16 round: [Cin,N] -> [N][32] half
        float* tb = reinterpret_cast<float*>(sbuf);   // [4][32][33]
        const int c8 = t >> 3, q = t & 7;
        const bool n4 = ((N & 3) == 0);

        float4 v[4];
        bool okv[4];
#pragma unroll
        for (int s = 0; s < 4; ++s) {
            int nb = (blk * 4 + s) * 32;
            okv[s] = n4 && (nb + 32 <= N);
            if (okv[s])
                v[s] = *reinterpret_cast<const float4*>(in + (size_t)c8 * N + nb + 4 * q);
        }
#pragma unroll
        for (int s = 0; s < 4; ++s) {
            int nb = (blk * 4 + s) * 32;
            float* tr = tb + s * 1056 + c8 * 33;
            if (okv[s]) {
                tr[4 * q + 0] = v[s].x;
                tr[4 * q + 1] = v[s].y;
                tr[4 * q + 2] = v[s].z;
                tr[4 * q + 3] = v[s].w;
            } else if (nb < N) {
#pragma unroll
                for (int e = 0; e < 4; ++e) {
                    int n = nb + 4 * q + e;
                    if (n < N) tr[4 * q + e] = in[(size_t)c8 * N + n];
                }
            }
        }
        __syncthreads();

        const int tx = t & 31, ty = t >> 5;
        const int cm = cin_of_f(tx);
#pragma unroll
        for (int s = 0; s < 4; ++s) {
            int nb = (blk * 4 + s) * 32;
            const float* tr = tb + s * 1056 + cm * 33;
#pragma unroll
            for (int j = 0; j < 4; ++j) {
                int nl = ty + 8 * j, n = nb + nl;
                if (n < N)
                    g_xTh[(size_t)n * CIN + tx] = __float2half_rn(tr[nl]);
            }
        }
        return;
    }
    blk -= nT;
    if (blk < nN) {
        // neigh transpose [N][27] -> [27][N]
        int warp = t >> 5, lane = t & 31;
        int* sw = reinterpret_cast<int*>(sbuf) + warp * 864;
        int base = (blk * 8 + warp) * 32;

        if (base + 32 <= N) {
            const int4* src = reinterpret_cast<const int4*>(neigh + (size_t)base * KTAP);
#pragma unroll
            for (int j = 0; j < 7; ++j) {
                int idx = j * 32 + lane;
                if (idx < 216) {
                    int4 vv = src[idx];
                    *reinterpret_cast<int4*>(sw + idx * 4) = vv;
                }
            }
        } else {
            const long fb = (long)base * KTAP;
            const long total = (long)N * KTAP;
#pragma unroll
            for (int j = 0; j < KTAP; ++j) {
                long p = fb + j * 32 + lane;
                sw[j * 32 + lane] = (p < total) ? neigh[p] : 0;
            }
        }
        __syncwarp();
        int node = base + lane;
        if (node < N) {
#pragma unroll
            for (int k = 0; k < KTAP; ++k)
                g_neighT[(size_t)k * N + node] = sw[lane * KTAP + k];
        }
        return;
    }
    blk -= nN;
    if (blk < nW) {
        if (blk == 0 && t < COUT) {
            g_sum[t] = 0.f;
            g_sq[t]  = 0.f;
        }
        int i = blk * blockDim.x + t;             // over 27*1024 halves
        if (i >= KTAP * 1024) return;
        int k = i >> 10, r = i & 1023;
        int n = r >> 5, f = r & 31;               // n = cout row, f = storage half
        int t8 = f >> 3, j = f & 7;
        int cin = 2 * t8 + 8 * (j >> 1) + (j & 1);
        int cph = t8 ^ ((n >> 1) & 3);            // smem swizzle baked in
        float v = w[((size_t)k * CIN + cin) * COUT + n];
        g_wpreh[k * 1024 + n * 32 + cph * 8 + j] = __float2half_rn(v);
    }
}

// ---------------- kernel 2: gather + mma.sync fp16 conv + fused BN stats ----------------
__global__ void __launch_bounds__(THREADS)
conv_mma_kernel(int N, int nchunks) {
    extern __shared__ char dsm[];
    __shared__ float s_sum[COUT], s_sq[COUT];
    const int tid  = threadIdx.x;
    const int warp = tid >> 5, lane = tid & 31;
    const int gid  = lane >> 2, tig = lane & 3;

    const uint32_t sbase = (smem_u32(dsm) + 1023u) & ~1023u;
    const uint32_t wbase = sbase;
    const uint32_t abase = sbase + W_BYTES + (uint32_t)warp * (NBUF * ABUF);

    if (tid < COUT) { s_sum[tid] = 0.f; s_sq[tid] = 0.f; }

    // ---- load all 27 pre-swizzled fp16 B tiles (one time) ----
    for (int i = tid; i < W_BYTES / 16; i += THREADS)
        cp16(wbase + i * 16, reinterpret_cast<const char*>(g_wpreh) + i * 16);
    CP_COMMIT();
    asm volatile("cp.async.wait_group 0;" ::: "memory");
    __syncthreads();

    float rs[4][2], rq[4][2];
#pragma unroll
    for (int nt = 0; nt < 4; ++nt) {
        rs[nt][0] = rs[nt][1] = 0.f;
        rq[nt][0] = rq[nt][1] = 0.f;
    }

    // per-warp work assignment, SM-striped
    const int wglob  = warp * gridDim.x + blockIdx.x;
    const int nwtot  = gridDim.x * NWARP;

    // per-lane B addresses (row nt*8+gid, chunk tig, swizzled) — loop-invariant
    uint32_t boff[4];
#pragma unroll
    for (int nt = 0; nt < 4; ++nt) {
        int brow = nt * 8 + gid;
        boff[nt] = (uint32_t)(brow << 6) + (uint32_t)((tig ^ ((brow >> 1) & 3)) << 4);
    }
    // per-lane A addresses (rows mt*16+gid, +8)
    uint32_t aoff[2][2];
#pragma unroll
    for (int mt = 0; mt < 2; ++mt) {
        int rlo = mt * 16 + gid, rhi = rlo + 8;
        aoff[mt][0] = (uint32_t)(rlo << 6) + (uint32_t)((tig ^ ((rlo >> 1) & 3)) << 4);
        aoff[mt][1] = (uint32_t)(rhi << 6) + (uint32_t)((tig ^ ((rhi >> 1) & 3)) << 4);
    }

    for (int ch = wglob; ch < nchunks; ch += nwtot) {
        const int base32 = ch << 5;
        const int mynode = base32 + lane;
        const bool nvalid = (mynode < N);

        float acc[2][4][4];
#pragma unroll
        for (int mt = 0; mt < 2; ++mt)
#pragma unroll
            for (int nt = 0; nt < 4; ++nt)
#pragma unroll
                for (int q = 0; q < 4; ++q) acc[mt][nt][q] = 0.f;

        // prologue: gather taps 0..1
#pragma unroll
        for (int k = 0; k < NBUF; ++k) {
            int idx = nvalid ? g_neighT[(size_t)k * N + mynode] : 0;
            gather32h(abase + (uint32_t)k * ABUF, idx, lane);
            CP_COMMIT();
        }

        int b = 0;
#pragma unroll 1
        for (int k = 0; k < KTAP; ++k) {
            if (k < KTAP - 1) asm volatile("cp.async.wait_group 1;" ::: "memory");
            else              asm volatile("cp.async.wait_group 0;" ::: "memory");
            __syncwarp();

            const uint32_t abuf = abase + (uint32_t)b * ABUF;
            const uint32_t wtap = wbase + (uint32_t)k * W_TILE;

            uint32_t B0[4], B1[4], B2[4], B3[4];
#pragma unroll
            for (int nt = 0; nt < 4; ++nt)
                lds4u(B0[nt], B1[nt], B2[nt], B3[nt], wtap + boff[nt]);
#pragma unroll
            for (int mt = 0; mt < 2; ++mt) {
                uint32_t x0, x1, x2, x3, y0, y1, y2, y3;
                lds4u(x0, x1, x2, x3, abuf + aoff[mt][0]);   // rows mt*16+gid
                lds4u(y0, y1, y2, y3, abuf + aoff[mt][1]);   // rows mt*16+gid+8
#pragma unroll
                for (int nt = 0; nt < 4; ++nt) {
                    mma16(acc[mt][nt], x0, y0, x1, y1, B0[nt], B1[nt]);   // k 0..15
                    mma16(acc[mt][nt], x2, y2, x3, y3, B2[nt], B3[nt]);   // k 16..31
                }
            }

            if (k + NBUF < KTAP) {
                __syncwarp();
                int idx = nvalid ? g_neighT[(size_t)(k + NBUF) * N + mynode] : 0;
                gather32h(abuf, idx, lane);
                CP_COMMIT();
            }
            b ^= 1;
        }

        // epilogue: store y + accumulate BN stats in registers
#pragma unroll
        for (int mt = 0; mt < 2; ++mt) {
            int node = base32 + (mt << 4) + gid;
            bool v0 = (node < N), v1 = (node + 8 < N);
#pragma unroll
            for (int nt = 0; nt < 4; ++nt) {
                int cb = (nt << 3) + (tig << 1);
                if (v0) {
                    float a = acc[mt][nt][0], c = acc[mt][nt][1];
                    g_y[(size_t)cb * N + node]       = a;
                    g_y[(size_t)(cb + 1) * N + node] = c;
                    rs[nt][0] += a; rq[nt][0] += a * a;
                    rs[nt][1] += c; rq[nt][1] += c * c;
                }
                if (v1) {
                    float a = acc[mt][nt][2], c = acc[mt][nt][3];
                    g_y[(size_t)cb * N + node + 8]       = a;
                    g_y[(size_t)(cb + 1) * N + node + 8] = c;
                    rs[nt][0] += a; rq[nt][0] += a * a;
                    rs[nt][1] += c; rq[nt][1] += c * c;
                }
            }
        }
    }

    // ---- reduce BN stats: shuffle over gid, shared atomics, one global atomic per CTA ----
#pragma unroll
    for (int nt = 0; nt < 4; ++nt)
#pragma unroll
        for (int q = 0; q < 2; ++q) {
#pragma unroll
            for (int o = 4; o <= 16; o <<= 1) {
                rs[nt][q] += __shfl_xor_sync(~0u, rs[nt][q], o);
                rq[nt][q] += __shfl_xor_sync(~0u, rq[nt][q], o);
            }
        }
    if (gid == 0) {
#pragma unroll
        for (int nt = 0; nt < 4; ++nt)
#pragma unroll
            for (int q = 0; q < 2; ++q) {
                int cb = (nt << 3) + (tig << 1) + q;
                atomicAdd(&s_sum[cb], rs[nt][q]);
                atomicAdd(&s_sq[cb],  rq[nt][q]);
            }
    }
    __syncthreads();
    if (tid < COUT) {
        atomicAdd(&g_sum[tid], s_sum[tid]);
        atomicAdd(&g_sq[tid],  s_sq[tid]);
    }
}

// ---------------- kernel 3: finalize (per-block) + normalize, 4 float4 per thread --------
__global__ void norm_kernel(float* __restrict__ out, const float* __restrict__ gamma,
                            const float* __restrict__ beta, int N) {
    __shared__ float s_scale[COUT], s_shift[COUT];
    if (threadIdx.x < COUT) {
        int d = threadIdx.x;
        float mean = g_sum[d] / (float)N;
        float var  = g_sq[d] / (float)N - mean * mean;
        float inv  = rsqrtf(var + BN_EPS);
        float sc   = gamma[d] * inv;
        s_scale[d] = sc;
        s_shift[d] = beta[d] - mean * sc;
    }
    __syncthreads();
    const int total4 = (COUT * N) >> 2;
    const int nq = N >> 2;
    int base = blockIdx.x * (blockDim.x * 4) + threadIdx.x;

    int    idx[4];
    float4 v[4];
    bool   ok[4];
#pragma unroll
    for (int u = 0; u < 4; ++u) {
        idx[u] = base + u * blockDim.x;
        ok[u] = (idx[u] < total4);
        if (ok[u]) v[u] = reinterpret_cast<const float4*>(g_y)[idx[u]];
    }
#pragma unroll
    for (int u = 0; u < 4; ++u) {
        if (!ok[u]) continue;
        int d = idx[u] / nq;
        float sc = s_scale[d], sh = s_shift[d];
        v[u].x = v[u].x * sc + sh;
        v[u].y = v[u].y * sc + sh;
        v[u].z = v[u].z * sc + sh;
        v[u].w = v[u].w * sc + sh;
        reinterpret_cast<float4*>(out)[idx[u]] = v[u];
    }
}

// ---------------- launch ----------------
extern "C" void kernel_launch(void* const* d_in, const int* in_sizes, int n_in,
                              void* d_out, int out_size) {
    const float* data_in = (const float*)d_in[0];   // [1, Cin, N, 1]
    const int*   neigh   = (const int*)d_in[1];     // [N, 27]
    const float* weight  = (const float*)d_in[2];   // [27, Cin, Cout]
    const float* gamma   = (const float*)d_in[3];
    const float* beta    = (const float*)d_in[4];
    float*       out     = (float*)d_out;

    const int N = in_sizes[0] / CIN;
    const int nchunks = (N + 31) / 32;

    int dev = 0, nsm = 148;
    cudaGetDevice(&dev);
    cudaDeviceGetAttribute(&nsm, cudaDevAttrMultiProcessorCount, dev);
    if (nsm <= 0) nsm = 148;
    int grid = nsm;
    int maxctas = (nchunks + NWARP - 1) / NWARP;
    if (grid > maxctas) grid = maxctas;

    cudaFuncSetAttribute(conv_mma_kernel,
                         cudaFuncAttributeMaxDynamicSharedMemorySize, DYN_SMEM);

    const int nT = (N + 127) / 128;                  // transpose blocks (4 subtiles each)
    const int nN = (N + 255) / 256;                  // neighT blocks
    const int nW = (KTAP * 1024 + 255) / 256;        // wprep blocks
    prep_kernel<<<nT + nN + nW, 256>>>(data_in, neigh, weight, N, nT, nN, nW);

    conv_mma_kernel<<<grid, THREADS, DYN_SMEM>>>(N, nchunks);

    {
        int total4 = (COUT * N) / 4;
        int nblk = (total4 + 1023) / 1024;
        norm_kernel<<<nblk, 256>>>(out, gamma, beta, N);
    }
}

// round 17
// speedup vs baseline: 1.5653x; 1.0440x over previous
#include <cuda_runtime.h>
#include <cuda_fp16.h>
#include <cstdint>

#define CIN     32
#define COUT    32
#define KTAP    27
#define THREADS 416
#define NWARP   13
#define MAX_N   131072
#define BN_EPS  1e-3f

#define W_TILE  2048            // one tap's B tile: 32 rows x 64B (fp16)
#define W_BYTES (KTAP * W_TILE) // 55296
#define ABUF    2048            // per-warp A buffer: 32 rows x 64B
#define NBUF    4
#define DYN_SMEM (1024 + W_BYTES + NWARP * NBUF * ABUF)   // 162816

// ---------------- device scratch ----------------
__device__ __align__(128) __half g_xTh[(size_t)MAX_N * CIN];  // x: [N][32] fp16, k-permuted
__device__ __align__(128) __half g_wpreh[KTAP * 1024];        // B tiles fp16, swizzled image
__device__ __align__(128) int    g_neighT[(size_t)KTAP * MAX_N];
__device__ __align__(128) float  g_y[(size_t)COUT * MAX_N];   // pre-BN result [Cout][N]
__device__ float g_sum[COUT];
__device__ float g_sq[COUT];

// k-permutation: storage half f (0..31) <-> original cin.
// chunk t = f>>3 holds k = {2t,2t+1, 2t+8,2t+9, 2t+16,2t+17, 2t+24,2t+25}
static __device__ __forceinline__ int cin_of_f(int f) {
    int t8 = f >> 3, j = f & 7;
    return 2 * t8 + 8 * (j >> 1) + (j & 1);
}

// ---------------- PTX helpers ----------------
static __device__ __forceinline__ uint32_t smem_u32(const void* p) {
    uint32_t a;
    asm("{ .reg .u64 t; cvta.to.shared.u64 t, %1; cvt.u32.u64 %0, t; }" : "=r"(a) : "l"(p));
    return a;
}
static __device__ __forceinline__ void cp16(uint32_t dst, const void* src) {
    asm volatile("cp.async.cg.shared.global [%0], [%1], 16;" :: "r"(dst), "l"(src) : "memory");
}
#define CP_COMMIT() asm volatile("cp.async.commit_group;" ::: "memory")

static __device__ __forceinline__ void lds4u(uint32_t& x, uint32_t& y, uint32_t& z, uint32_t& w,
                                             uint32_t a) {
    asm volatile("ld.shared.v4.b32 {%0,%1,%2,%3}, [%4];"
                 : "=r"(x), "=r"(y), "=r"(z), "=r"(w) : "r"(a));
}
static __device__ __forceinline__ void mma16(float* c, uint32_t a0, uint32_t a1, uint32_t a2,
                                             uint32_t a3, uint32_t b0, uint32_t b1) {
    asm volatile(
        "mma.sync.aligned.m16n8k16.row.col.f32.f16.f16.f32 "
        "{%0,%1,%2,%3}, {%4,%5,%6,%7}, {%8,%9}, {%0,%1,%2,%3};"
        : "+f"(c[0]), "+f"(c[1]), "+f"(c[2]), "+f"(c[3])
        : "r"(a0), "r"(a1), "r"(a2), "r"(a3), "r"(b0), "r"(b1));
}

// cooperative gather: one warp fills 32 rows (64B each); each cp.async covers
// 8 rows x 4 lanes; writes conflict-free (swizzle chunk ^ ((row>>1)&3)).
static __device__ __forceinline__ void gather32h(uint32_t dst_buf, int idx_reg, int lane) {
    const int rsub  = lane >> 2;       // 0..7
    const int chunk = lane & 3;        // 16B chunk within 64B row
#pragma unroll
    for (int j = 0; j < 4; ++j) {
        int row = j * 8 + rsub;
        int src_idx = __shfl_sync(0xffffffffu, idx_reg, row);
        const char* src = reinterpret_cast<const char*>(g_xTh + (size_t)src_idx * CIN)
                          + (chunk << 4);
        uint32_t dst = dst_buf + (uint32_t)(row << 6)
                       + (uint32_t)((chunk ^ ((row >> 1) & 3)) << 4);
        cp16(dst, src);
    }
}

// ---------------- kernel 1: fused prep (transpose | neighT | wprep+init) ----------------
__global__ void prep_kernel(const float* __restrict__ in, const int* __restrict__ neigh,
                            const float* __restrict__ w, int N,
                            int nT, int nN, int nW) {
    __shared__ __align__(16) char sbuf[8 * 864 * 4];
    int blk = blockIdx.x;
    int t = threadIdx.x;

    if (blk < nT) {
        // transpose + k-permute + fp16 round: [Cin,N] -> [N][32] half
        float* tb = reinterpret_cast<float*>(sbuf);   // [4][32][33]
        const int c8 = t >> 3, q = t & 7;
        const bool n4 = ((N & 3) == 0);

        float4 v[4];
        bool okv[4];
#pragma unroll
        for (int s = 0; s < 4; ++s) {
            int nb = (blk * 4 + s) * 32;
            okv[s] = n4 && (nb + 32 <= N);
            if (okv[s])
                v[s] = *reinterpret_cast<const float4*>(in + (size_t)c8 * N + nb + 4 * q);
        }
#pragma unroll
        for (int s = 0; s < 4; ++s) {
            int nb = (blk * 4 + s) * 32;
            float* tr = tb + s * 1056 + c8 * 33;
            if (okv[s]) {
                tr[4 * q + 0] = v[s].x;
                tr[4 * q + 1] = v[s].y;
                tr[4 * q + 2] = v[s].z;
                tr[4 * q + 3] = v[s].w;
            } else if (nb < N) {
#pragma unroll
                for (int e = 0; e < 4; ++e) {
                    int n = nb + 4 * q + e;
                    if (n < N) tr[4 * q + e] = in[(size_t)c8 * N + n];
                }
            }
        }
        __syncthreads();

        const int tx = t & 31, ty = t >> 5;
        const int cm = cin_of_f(tx);
#pragma unroll
        for (int s = 0; s < 4; ++s) {
            int nb = (blk * 4 + s) * 32;
            const float* tr = tb + s * 1056 + cm * 33;
#pragma unroll
            for (int j = 0; j < 4; ++j) {
                int nl = ty + 8 * j, n = nb + nl;
                if (n < N)
                    g_xTh[(size_t)n * CIN + tx] = __float2half_rn(tr[nl]);
            }
        }
        return;
    }
    blk -= nT;
    if (blk < nN) {
        // neigh transpose [N][27] -> [27][N]
        int warp = t >> 5, lane = t & 31;
        int* sw = reinterpret_cast<int*>(sbuf) + warp * 864;
        int base = (blk * 8 + warp) * 32;

        if (base + 32 <= N) {
            const int4* src = reinterpret_cast<const int4*>(neigh + (size_t)base * KTAP);
#pragma unroll
            for (int j = 0; j < 7; ++j) {
                int idx = j * 32 + lane;
                if (idx < 216) {
                    int4 vv = src[idx];
                    *reinterpret_cast<int4*>(sw + idx * 4) = vv;
                }
            }
        } else {
            const long fb = (long)base * KTAP;
            const long total = (long)N * KTAP;
#pragma unroll
            for (int j = 0; j < KTAP; ++j) {
                long p = fb + j * 32 + lane;
                sw[j * 32 + lane] = (p < total) ? neigh[p] : 0;
            }
        }
        __syncwarp();
        int node = base + lane;
        if (node < N) {
#pragma unroll
            for (int k = 0; k < KTAP; ++k)
                g_neighT[(size_t)k * N + node] = sw[lane * KTAP + k];
        }
        return;
    }
    blk -= nN;
    if (blk < nW) {
        if (blk == 0 && t < COUT) {
            g_sum[t] = 0.f;
            g_sq[t]  = 0.f;
        }
        int i = blk * blockDim.x + t;             // over 27*1024 halves
        if (i >= KTAP * 1024) return;
        int k = i >> 10, r = i & 1023;
        int n = r >> 5, f = r & 31;               // n = cout row, f = storage half
        int t8 = f >> 3, j = f & 7;
        int cin = 2 * t8 + 8 * (j >> 1) + (j & 1);
        int cph = t8 ^ ((n >> 1) & 3);            // smem swizzle baked in
        float v = w[((size_t)k * CIN + cin) * COUT + n];
        g_wpreh[k * 1024 + n * 32 + cph * 8 + j] = __float2half_rn(v);
    }
}

// ---------------- kernel 2: gather + mma.sync fp16 conv + fused BN stats ----------------
__global__ void __launch_bounds__(THREADS)
conv_mma_kernel(int N, int nchunks) {
    extern __shared__ char dsm[];
    __shared__ float s_sum[COUT], s_sq[COUT];
    const int tid  = threadIdx.x;
    const int warp = tid >> 5, lane = tid & 31;
    const int gid  = lane >> 2, tig = lane & 3;

    const uint32_t sbase = (smem_u32(dsm) + 1023u) & ~1023u;
    const uint32_t wbase = sbase;
    const uint32_t abase = sbase + W_BYTES + (uint32_t)warp * (NBUF * ABUF);

    if (tid < COUT) { s_sum[tid] = 0.f; s_sq[tid] = 0.f; }

    // ---- load all 27 pre-swizzled fp16 B tiles (one time) ----
    for (int i = tid; i < W_BYTES / 16; i += THREADS)
        cp16(wbase + i * 16, reinterpret_cast<const char*>(g_wpreh) + i * 16);
    CP_COMMIT();
    asm volatile("cp.async.wait_group 0;" ::: "memory");
    __syncthreads();

    float rs[4][2], rq[4][2];
#pragma unroll
    for (int nt = 0; nt < 4; ++nt) {
        rs[nt][0] = rs[nt][1] = 0.f;
        rq[nt][0] = rq[nt][1] = 0.f;
    }

    // per-warp work assignment, SM-striped
    const int wglob  = warp * gridDim.x + blockIdx.x;
    const int nwtot  = gridDim.x * NWARP;

    // per-lane B addresses (row nt*8+gid, chunk tig, swizzled) — loop-invariant
    uint32_t boff[4];
#pragma unroll
    for (int nt = 0; nt < 4; ++nt) {
        int brow = nt * 8 + gid;
        boff[nt] = (uint32_t)(brow << 6) + (uint32_t)((tig ^ ((brow >> 1) & 3)) << 4);
    }
    // per-lane A addresses (rows mt*16+gid, +8)
    uint32_t aoff[2][2];
#pragma unroll
    for (int mt = 0; mt < 2; ++mt) {
        int rlo = mt * 16 + gid, rhi = rlo + 8;
        aoff[mt][0] = (uint32_t)(rlo << 6) + (uint32_t)((tig ^ ((rlo >> 1) & 3)) << 4);
        aoff[mt][1] = (uint32_t)(rhi << 6) + (uint32_t)((tig ^ ((rhi >> 1) & 3)) << 4);
    }

    for (int ch = wglob; ch < nchunks; ch += nwtot) {
        const int base32 = ch << 5;
        const int mynode = base32 + lane;
        const bool nvalid = (mynode < N);

        float acc[2][4][4];
#pragma unroll
        for (int mt = 0; mt < 2; ++mt)
#pragma unroll
            for (int nt = 0; nt < 4; ++nt)
#pragma unroll
                for (int q = 0; q < 4; ++q) acc[mt][nt][q] = 0.f;

        // prologue: gather taps 0..NBUF-1
#pragma unroll
        for (int k = 0; k < NBUF; ++k) {
            int idx = nvalid ? g_neighT[(size_t)k * N + mynode] : 0;
            gather32h(abase + (uint32_t)k * ABUF, idx, lane);
            CP_COMMIT();
        }

        int b = 0;
#pragma unroll 1
        for (int k = 0; k < KTAP; ++k) {
            // wait until tap k's gather group has landed (allow min(NBUF-1, KTAP-1-k) outstanding)
            if (k < KTAP - 3)       asm volatile("cp.async.wait_group 3;" ::: "memory");
            else if (k == KTAP - 3) asm volatile("cp.async.wait_group 2;" ::: "memory");
            else if (k == KTAP - 2) asm volatile("cp.async.wait_group 1;" ::: "memory");
            else                    asm volatile("cp.async.wait_group 0;" ::: "memory");
            __syncwarp();

            const uint32_t abuf = abase + (uint32_t)b * ABUF;
            const uint32_t wtap = wbase + (uint32_t)k * W_TILE;

            uint32_t B0[4], B1[4], B2[4], B3[4];
#pragma unroll
            for (int nt = 0; nt < 4; ++nt)
                lds4u(B0[nt], B1[nt], B2[nt], B3[nt], wtap + boff[nt]);
#pragma unroll
            for (int mt = 0; mt < 2; ++mt) {
                uint32_t x0, x1, x2, x3, y0, y1, y2, y3;
                lds4u(x0, x1, x2, x3, abuf + aoff[mt][0]);   // rows mt*16+gid
                lds4u(y0, y1, y2, y3, abuf + aoff[mt][1]);   // rows mt*16+gid+8
#pragma unroll
                for (int nt = 0; nt < 4; ++nt) {
                    mma16(acc[mt][nt], x0, y0, x1, y1, B0[nt], B1[nt]);   // k 0..15
                    mma16(acc[mt][nt], x2, y2, x3, y3, B2[nt], B3[nt]);   // k 16..31
                }
            }

            if (k + NBUF < KTAP) {
                __syncwarp();
                int idx = nvalid ? g_neighT[(size_t)(k + NBUF) * N + mynode] : 0;
                gather32h(abuf, idx, lane);
                CP_COMMIT();
            }
            b = (b + 1) & (NBUF - 1);
        }

        // epilogue: store y + accumulate BN stats in registers
#pragma unroll
        for (int mt = 0; mt < 2; ++mt) {
            int node = base32 + (mt << 4) + gid;
            bool v0 = (node < N), v1 = (node + 8 < N);
#pragma unroll
            for (int nt = 0; nt < 4; ++nt) {
                int cb = (nt << 3) + (tig << 1);
                if (v0) {
                    float a = acc[mt][nt][0], c = acc[mt][nt][1];
                    g_y[(size_t)cb * N + node]       = a;
                    g_y[(size_t)(cb + 1) * N + node] = c;
                    rs[nt][0] += a; rq[nt][0] += a * a;
                    rs[nt][1] += c; rq[nt][1] += c * c;
                }
                if (v1) {
                    float a = acc[mt][nt][2], c = acc[mt][nt][3];
                    g_y[(size_t)cb * N + node + 8]       = a;
                    g_y[(size_t)(cb + 1) * N + node + 8] = c;
                    rs[nt][0] += a; rq[nt][0] += a * a;
                    rs[nt][1] += c; rq[nt][1] += c * c;
                }
            }
        }
    }

    // ---- reduce BN stats: shuffle over gid, shared atomics, one global atomic per CTA ----
#pragma unroll
    for (int nt = 0; nt < 4; ++nt)
#pragma unroll
        for (int q = 0; q < 2; ++q) {
#pragma unroll
            for (int o = 4; o <= 16; o <<= 1) {
                rs[nt][q] += __shfl_xor_sync(~0u, rs[nt][q], o);
                rq[nt][q] += __shfl_xor_sync(~0u, rq[nt][q], o);
            }
        }
    if (gid == 0) {
#pragma unroll
        for (int nt = 0; nt < 4; ++nt)
#pragma unroll
            for (int q = 0; q < 2; ++q) {
                int cb = (nt << 3) + (tig << 1) + q;
                atomicAdd(&s_sum[cb], rs[nt][q]);
                atomicAdd(&s_sq[cb],  rq[nt][q]);
            }
    }
    __syncthreads();
    if (tid < COUT) {
        atomicAdd(&g_sum[tid], s_sum[tid]);
        atomicAdd(&g_sq[tid],  s_sq[tid]);
    }
}

// ---------------- kernel 3: finalize (per-block) + normalize, 4 float4 per thread --------
__global__ void norm_kernel(float* __restrict__ out, const float* __restrict__ gamma,
                            const float* __restrict__ beta, int N) {
    __shared__ float s_scale[COUT], s_shift[COUT];
    if (threadIdx.x < COUT) {
        int d = threadIdx.x;
        float mean = g_sum[d] / (float)N;
        float var  = g_sq[d] / (float)N - mean * mean;
        float inv  = rsqrtf(var + BN_EPS);
        float sc   = gamma[d] * inv;
        s_scale[d] = sc;
        s_shift[d] = beta[d] - mean * sc;
    }
    __syncthreads();
    const int total4 = (COUT * N) >> 2;
    const int nq = N >> 2;
    int base = blockIdx.x * (blockDim.x * 4) + threadIdx.x;

    int    idx[4];
    float4 v[4];
    bool   ok[4];
#pragma unroll
    for (int u = 0; u < 4; ++u) {
        idx[u] = base + u * blockDim.x;
        ok[u] = (idx[u] < total4);
        if (ok[u]) v[u] = reinterpret_cast<const float4*>(g_y)[idx[u]];
    }
#pragma unroll
    for (int u = 0; u < 4; ++u) {
        if (!ok[u]) continue;
        int d = idx[u] / nq;
        float sc = s_scale[d], sh = s_shift[d];
        v[u].x = v[u].x * sc + sh;
        v[u].y = v[u].y * sc + sh;
        v[u].z = v[u].z * sc + sh;
        v[u].w = v[u].w * sc + sh;
        reinterpret_cast<float4*>(out)[idx[u]] = v[u];
    }
}

// ---------------- launch ----------------
extern "C" void kernel_launch(void* const* d_in, const int* in_sizes, int n_in,
                              void* d_out, int out_size) {
    const float* data_in = (const float*)d_in[0];   // [1, Cin, N, 1]
    const int*   neigh   = (const int*)d_in[1];     // [N, 27]
    const float* weight  = (const float*)d_in[2];   // [27, Cin, Cout]
    const float* gamma   = (const float*)d_in[3];
    const float* beta    = (const float*)d_in[4];
    float*       out     = (float*)d_out;

    const int N = in_sizes[0] / CIN;
    const int nchunks = (N + 31) / 32;

    int dev = 0, nsm = 148;
    cudaGetDevice(&dev);
    cudaDeviceGetAttribute(&nsm, cudaDevAttrMultiProcessorCount, dev);
    if (nsm <= 0) nsm = 148;
    int grid = nsm;
    int maxctas = (nchunks + NWARP - 1) / NWARP;
    if (grid > maxctas) grid = maxctas;

    cudaFuncSetAttribute(conv_mma_kernel,
                         cudaFuncAttributeMaxDynamicSharedMemorySize, DYN_SMEM);

    const int nT = (N + 127) / 128;                  // transpose blocks (4 subtiles each)
    const int nN = (N + 255) / 256;                  // neighT blocks
    const int nW = (KTAP * 1024 + 255) / 256;        // wprep blocks
    prep_kernel<<<nT + nN + nW, 256>>>(data_in, neigh, weight, N, nT, nN, nW);

    conv_mma_kernel<<<grid, THREADS, DYN_SMEM>>>(N, nchunks);

    {
        int total4 = (COUT * N) / 4;
        int nblk = (total4 + 1023) / 1024;
        norm_kernel<<<nblk, 256>>>(out, gamma, beta, N);
    }
}